// round 10
// baseline (speedup 1.0000x reference)
#include <cuda_runtime.h>
#include <cuda_bf16.h>
#include <cmath>

#define B_ 32
#define N_ 16384
#define D_ 64
#define S_ 8
#define H_ 128
#define LNEPS 1e-5f
#define ATTN_EPS 1e-8f

typedef unsigned long long ull;
typedef unsigned int u32;

// ---------------- scratch (device globals; no allocations allowed) ----------
__device__ unsigned g_kh[B_ * N_ * 32];   // k_pos bf16x2 (64 MB)
__device__ unsigned g_vh[B_ * N_ * 32];   // v_pos bf16x2 (64 MB)
__device__ unsigned g_tkb[B_ * N_ * 32];  // LN(k+gp) bf16x2 intermediate (64 MB)
__device__ unsigned g_tvb[B_ * N_ * 32];  // LN(v+gp) bf16x2 intermediate (64 MB)
__device__ float g_q[B_ * S_ * D_];
__device__ float g_s[B_ * S_ * D_];
__device__ float g_part[B_ * 64 * 520];   // per-(b, partial-block) numer(512)+den(8)

// ---------------- helpers ----------------------------------------------------
__device__ __forceinline__ unsigned bf2u(float a, float b) {
    __nv_bfloat162 h = __float22bfloat162_rn(make_float2(a, b));
    return *(unsigned*)&h;
}
__device__ __forceinline__ float2 u2f2(unsigned u) {
    __nv_bfloat162 h = *(__nv_bfloat162*)&u;
    return __bfloat1622float2(h);
}
__device__ __forceinline__ void ldsm_x4(u32 a[4], u32 addr) {
    asm volatile("ldmatrix.sync.aligned.m8n8.x4.shared.b16 {%0,%1,%2,%3}, [%4];"
                 : "=r"(a[0]), "=r"(a[1]), "=r"(a[2]), "=r"(a[3]) : "r"(addr));
}
__device__ __forceinline__ void ldsm_x2t(u32 b[2], u32 addr) {
    asm volatile("ldmatrix.sync.aligned.m8n8.x2.trans.shared.b16 {%0,%1}, [%2];"
                 : "=r"(b[0]), "=r"(b[1]) : "r"(addr));
}
__device__ __forceinline__ void mma_bf16(float d[4], const u32 a[4], const u32 b[2]) {
    asm volatile("mma.sync.aligned.m16n8k16.row.col.f32.bf16.bf16.f32 "
                 "{%0,%1,%2,%3},{%4,%5,%6,%7},{%8,%9},{%0,%1,%2,%3};"
                 : "+f"(d[0]), "+f"(d[1]), "+f"(d[2]), "+f"(d[3])
                 : "r"(a[0]), "r"(a[1]), "r"(a[2]), "r"(a[3]), "r"(b[0]), "r"(b[1]));
}

// ---------------------------------------------------------------------------
// Phase A: input LN -> fused k/v GEMM1 + grid proj -> pe-LN -> bf16 gmem.
// Shuffle-free LN (stats by thread-groups, normalize coalesced).
// smem bytes:
//   sWk  @     0 : 9216   (64x72 bf16)
//   sWv  @  9216 : 9216
//   sX   @ 18432 : 9216   (64x72 bf16)
//   sIn/sTfk @ 27648 : 16896 (64x66 f32; input tile aliased with Tf_k)
//   sTfv @ 44544 : 16896
//   sV   @ 61440 : 1792   (448 f32: pa0,pa1,pab,lng,lnb,peg,peb)
//   sG   @ 63232 : 512    (128 f32)
//   sMu  @ 63744 : 512    (128 f32)
//   sRs  @ 64256 : 512    -> total 64768 B (3 CTAs/SM)
// ---------------------------------------------------------------------------
#define PA_SMEM_BYTES 64768

__global__ __launch_bounds__(256, 3) void phaseA_kernel(
    const float* __restrict__ inp,
    const float* __restrict__ lng, const float* __restrict__ lnb,
    const float* __restrict__ Wk,  const float* __restrict__ Wv,
    const float* __restrict__ paW, const float* __restrict__ pab,
    const float* __restrict__ peg, const float* __restrict__ peb)
{
    extern __shared__ char smem[];
    __nv_bfloat16* sWk = (__nv_bfloat16*)(smem);
    __nv_bfloat16* sWv = (__nv_bfloat16*)(smem + 9216);
    __nv_bfloat16* sX  = (__nv_bfloat16*)(smem + 18432);
    float*         sIn = (float*)(smem + 27648);
    float*         sTfk = (float*)(smem + 27648);   // alias
    float*         sTfv = (float*)(smem + 44544);
    float*         sV  = (float*)(smem + 61440);
    float*         sG  = (float*)(smem + 63232);
    float*         sMu = (float*)(smem + 63744);
    float*         sRs = (float*)(smem + 64256);

    u32 sb = (u32)__cvta_generic_to_shared(smem);
    const u32 sbWk = sb, sbWv = sb + 9216, sbX = sb + 18432;

    const int t = threadIdx.x, warp = t >> 5, lane = t & 31;
    const int mt = warp >> 1, ng = warp & 1;
    const int l15 = lane & 15, lh = lane >> 4, lr = lane >> 2, lc = (lane & 3) * 2;

    for (int i = t; i < 4096; i += 256) {
        int r = i >> 6, c = i & 63;
        sWk[r * 72 + c] = __float2bfloat16(Wk[i]);
        sWv[r * 72 + c] = __float2bfloat16(Wv[i]);
    }
    if (t < 64) {
        sV[t]       = paW[t];
        sV[64 + t]  = paW[64 + t];
        sV[128 + t] = pab[t];
        sV[192 + t] = lng[t];
        sV[256 + t] = lnb[t];
        sV[320 + t] = peg[t];
        sV[384 + t] = peb[t];
    }
    __syncthreads();

    for (int ti = 0; ti < 4; ti++) {
        int tile = blockIdx.x * 4 + ti;          // 8192 tiles of 64 rows
        int rowbase = tile * 64;

        // ---- coalesced copy-in: 64 rows x 66 floats (contiguous) ----
        {
            const float4* in4 = (const float4*)(inp + (size_t)rowbase * 66);
            float4* s4 = (float4*)sIn;
            #pragma unroll
            for (int i = 0; i < 4; i++) s4[t + i * 256] = in4[t + i * 256];
            if (t < 32) s4[t + 1024] = in4[t + 1024];
        }
        __syncthreads();

        // ---- stats1: 4 threads per row (16 cols each), depth-2 shuffle ----
        {
            int r = t >> 2, q = t & 3;
            const float* p = sIn + r * 66 + q * 16;
            float s1 = 0.f, s2 = 0.f;
            #pragma unroll
            for (int j = 0; j < 8; j++) {
                float2 x = *(const float2*)(p + 2 * j);
                s1 += x.x + x.y; s2 += x.x * x.x + x.y * x.y;
            }
            s1 += __shfl_xor_sync(0xffffffffu, s1, 1);
            s2 += __shfl_xor_sync(0xffffffffu, s2, 1);
            s1 += __shfl_xor_sync(0xffffffffu, s1, 2);
            s2 += __shfl_xor_sync(0xffffffffu, s2, 2);
            if (q == 0) {
                float mu = s1 * 0.015625f;
                float var = s2 * 0.015625f - mu * mu;
                sMu[r] = mu; sRs[r] = rsqrtf(var + LNEPS);
            }
            if (t < 128) sG[t] = sIn[(t >> 1) * 66 + 64 + (t & 1)];
        }
        __syncthreads();

        // ---- normalize1 -> bf16 sX (no shuffles) ----
        for (int rr = warp; rr < 64; rr += 8) {
            float mu = sMu[rr], rs = sRs[rr];
            float x0 = sIn[rr * 66 + lane], x1 = sIn[rr * 66 + lane + 32];
            sX[rr * 72 + lane]      = __float2bfloat16((x0 - mu) * rs * sV[192 + lane]      + sV[256 + lane]);
            sX[rr * 72 + lane + 32] = __float2bfloat16((x1 - mu) * rs * sV[192 + lane + 32] + sV[256 + lane + 32]);
        }
        __syncthreads();

        // ---- fused GEMM1 (tensor): Tfk = X@Wk + gp, Tfv = X@Wv + gp ----
        {
            float accK[4][4], accV[4][4];
            #pragma unroll
            for (int s = 0; s < 4; s++)
                #pragma unroll
                for (int j = 0; j < 4; j++) { accK[s][j] = 0.f; accV[s][j] = 0.f; }

            #pragma unroll
            for (int ks = 0; ks < 4; ks++) {
                u32 a[4];
                ldsm_x4(a, sbX + ((mt * 16 + l15) * 72 + ks * 16 + lh * 8) * 2);
                #pragma unroll
                for (int s = 0; s < 4; s++) {
                    u32 bk[2], bv[2];
                    int nb = ng * 32 + s * 8;
                    ldsm_x2t(bk, sbWk + ((ks * 16 + l15) * 72 + nb) * 2);
                    ldsm_x2t(bv, sbWv + ((ks * 16 + l15) * 72 + nb) * 2);
                    mma_bf16(accK[s], a, bk);
                    mma_bf16(accV[s], a, bv);
                }
            }
            int r0 = mt * 16 + lr, r1 = r0 + 8;
            float gx0 = sG[r0 * 2], gy0 = sG[r0 * 2 + 1];
            float gx1 = sG[r1 * 2], gy1 = sG[r1 * 2 + 1];
            #pragma unroll
            for (int s = 0; s < 4; s++) {
                int c = ng * 32 + s * 8 + lc;
                float p0a = sV[c], p0b = sV[c + 1];
                float p1a = sV[64 + c], p1b = sV[64 + c + 1];
                float pba = sV[128 + c], pbb = sV[128 + c + 1];
                float g0a = gx0 * p0a + gy0 * p1a + pba;
                float g0b = gx0 * p0b + gy0 * p1b + pbb;
                float g1a = gx1 * p0a + gy1 * p1a + pba;
                float g1b = gx1 * p0b + gy1 * p1b + pbb;
                *(float2*)&sTfk[r0 * 66 + c] = make_float2(accK[s][0] + g0a, accK[s][1] + g0b);
                *(float2*)&sTfk[r1 * 66 + c] = make_float2(accK[s][2] + g1a, accK[s][3] + g1b);
                *(float2*)&sTfv[r0 * 66 + c] = make_float2(accV[s][0] + g0a, accV[s][1] + g0b);
                *(float2*)&sTfv[r1 * 66 + c] = make_float2(accV[s][2] + g1a, accV[s][3] + g1b);
            }
        }
        __syncthreads();

        // ---- stats2: 2 threads per row (128 rows), depth-1 shuffle ----
        {
            int r = t >> 1, h = t & 1;
            const float* base = (r < 64 ? sTfk + r * 66 : sTfv + (r - 64) * 66) + h * 32;
            float s1 = 0.f, s2 = 0.f;
            #pragma unroll
            for (int j = 0; j < 16; j++) {
                float2 x = *(const float2*)(base + 2 * j);
                s1 += x.x + x.y; s2 += x.x * x.x + x.y * x.y;
            }
            s1 += __shfl_xor_sync(0xffffffffu, s1, 1);
            s2 += __shfl_xor_sync(0xffffffffu, s2, 1);
            if (h == 0) {
                float mu = s1 * 0.015625f;
                float var = s2 * 0.015625f - mu * mu;
                sMu[r] = mu; sRs[r] = rsqrtf(var + LNEPS);
            }
        }
        __syncthreads();

        // ---- normalize2 (pe LN) -> packed bf16x2 gmem ----
        for (int rr = warp; rr < 128; rr += 8) {
            int r = rr & 63;
            const float* Tf = (rr < 64) ? sTfk : sTfv;
            unsigned* og = (rr < 64) ? g_tkb : g_tvb;
            float mu = sMu[rr], rs = sRs[rr];
            float2 x = *(const float2*)(Tf + r * 66 + 2 * lane);
            int c = 2 * lane;
            float y0 = (x.x - mu) * rs * sV[320 + c]     + sV[384 + c];
            float y1 = (x.y - mu) * rs * sV[320 + c + 1] + sV[384 + c + 1];
            og[(size_t)(rowbase + r) * 32 + lane] = bf2u(y0, y1);
        }
        __syncthreads();
    }
}

// ---------------------------------------------------------------------------
// Phase B: MLP streamer. H = relu(T@W1+b1); out = H@W2+b2. 16384 tiles
// (k stream then v stream).
// smem: sW1 @0 (17408) | sW2 @17408 (18432) | sTb @35840 (9216) |
//       sHb @45056 (17408) | sV @62464 (768) -> 63232 B (3 CTAs/SM)
// ---------------------------------------------------------------------------
#define PB_SMEM_BYTES 63232

__global__ __launch_bounds__(256, 3) void phaseB_kernel(
    const float* __restrict__ W1, const float* __restrict__ b1,
    const float* __restrict__ W2, const float* __restrict__ b2)
{
    extern __shared__ char smem[];
    __nv_bfloat16* sW1 = (__nv_bfloat16*)(smem);
    __nv_bfloat16* sW2 = (__nv_bfloat16*)(smem + 17408);
    __nv_bfloat16* sTb = (__nv_bfloat16*)(smem + 35840);
    __nv_bfloat16* sHb = (__nv_bfloat16*)(smem + 45056);
    float*         sV  = (float*)(smem + 62464);

    u32 sb = (u32)__cvta_generic_to_shared(smem);
    const u32 sbW1 = sb, sbW2 = sb + 17408, sbTb = sb + 35840, sbHb = sb + 45056;

    const int t = threadIdx.x, warp = t >> 5, lane = t & 31;
    const int mt = warp >> 1, ng = warp & 1;
    const int l15 = lane & 15, lh = lane >> 4, lr = lane >> 2, lc = (lane & 3) * 2;

    for (int i = t; i < 8192; i += 256) {
        int r1_ = i >> 7, c1_ = i & 127;
        sW1[r1_ * 136 + c1_] = __float2bfloat16(W1[i]);
        int r2_ = i >> 6, c2_ = i & 63;
        sW2[r2_ * 72 + c2_] = __float2bfloat16(W2[i]);
    }
    if (t < 128) sV[t] = b1[t];
    if (t < 64)  sV[128 + t] = b2[t];
    __syncthreads();

    for (int ti = 0; ti < 4; ti++) {
        int tile = blockIdx.x * 4 + ti;        // 0..16383
        int strm = tile >> 13;
        int idx  = tile & 8191;
        const unsigned* ing = strm ? g_tvb : g_tkb;
        unsigned* outg = strm ? g_vh : g_kh;
        size_t rowbase = (size_t)idx * 64;

        // ---- load tile bf16x2 -> padded smem ----
        {
            u32* d = (u32*)sTb;
            const unsigned* src = ing + rowbase * 32;
            #pragma unroll
            for (int i = 0; i < 8; i++) {
                int idx2 = t + i * 256;
                int r = idx2 >> 5, c = idx2 & 31;
                d[r * 36 + c] = src[idx2];
            }
        }
        __syncthreads();

        // ---- GEMM2: H = relu(T @ W1 + b1) ----
        {
            float acc[8][4];
            #pragma unroll
            for (int s = 0; s < 8; s++)
                #pragma unroll
                for (int j = 0; j < 4; j++) acc[s][j] = 0.f;

            #pragma unroll
            for (int ks = 0; ks < 4; ks++) {
                u32 a[4];
                ldsm_x4(a, sbTb + ((mt * 16 + l15) * 72 + ks * 16 + lh * 8) * 2);
                #pragma unroll
                for (int s = 0; s < 8; s++) {
                    u32 b[2];
                    int nb = ng * 64 + s * 8;
                    ldsm_x2t(b, sbW1 + ((ks * 16 + l15) * 136 + nb) * 2);
                    mma_bf16(acc[s], a, b);
                }
            }
            int r0 = mt * 16 + lr, r1 = r0 + 8;
            #pragma unroll
            for (int s = 0; s < 8; s++) {
                int c = ng * 64 + s * 8 + lc;
                float ba = sV[c], bb = sV[c + 1];
                *(u32*)&sHb[r0 * 136 + c] =
                    bf2u(fmaxf(acc[s][0] + ba, 0.f), fmaxf(acc[s][1] + bb, 0.f));
                *(u32*)&sHb[r1 * 136 + c] =
                    bf2u(fmaxf(acc[s][2] + ba, 0.f), fmaxf(acc[s][3] + bb, 0.f));
            }
        }
        __syncthreads();

        // ---- GEMM3: out = H @ W2 + b2 -> bf16x2 gmem ----
        {
            float acc[4][4];
            #pragma unroll
            for (int s = 0; s < 4; s++)
                #pragma unroll
                for (int j = 0; j < 4; j++) acc[s][j] = 0.f;

            #pragma unroll
            for (int ks = 0; ks < 8; ks++) {
                u32 a[4];
                ldsm_x4(a, sbHb + ((mt * 16 + l15) * 136 + ks * 16 + lh * 8) * 2);
                #pragma unroll
                for (int s = 0; s < 4; s++) {
                    u32 b[2];
                    int nb = ng * 32 + s * 8;
                    ldsm_x2t(b, sbW2 + ((ks * 16 + l15) * 72 + nb) * 2);
                    mma_bf16(acc[s], a, b);
                }
            }
            int r0 = mt * 16 + lr, r1 = r0 + 8;
            #pragma unroll
            for (int s = 0; s < 4; s++) {
                int c = ng * 32 + s * 8 + lc;
                float ba = sV[128 + c], bb = sV[128 + c + 1];
                outg[(size_t)(rowbase + r0) * 32 + (c >> 1)] =
                    bf2u(acc[s][0] + ba, acc[s][1] + bb);
                outg[(size_t)(rowbase + r1) * 32 + (c >> 1)] =
                    bf2u(acc[s][2] + ba, acc[s][3] + bb);
            }
        }
        __syncthreads();
    }
}

// ---------------------------------------------------------------------------
// Kernel: init slot state
// ---------------------------------------------------------------------------
__global__ void init_slots_kernel(const float* __restrict__ slots)
{
    g_s[blockIdx.x * 512 + threadIdx.x] = slots[threadIdx.x];
}

// ---------------------------------------------------------------------------
// Kernel: q = LN(s; ln_s) @ Wq  (one block per b)
// ---------------------------------------------------------------------------
__global__ __launch_bounds__(256) void slotq_kernel(
    const float* __restrict__ lnsg, const float* __restrict__ lnsb,
    const float* __restrict__ Wq)
{
    __shared__ float sln[512];
    int b = blockIdx.x, t = threadIdx.x, warp = t >> 5, lane = t & 31;
    {
        const float* row = g_s + b * 512 + warp * 64;
        float x0 = row[lane], x1 = row[lane + 32];
        float s1 = x0 + x1, s2 = x0 * x0 + x1 * x1;
        #pragma unroll
        for (int o = 16; o; o >>= 1) {
            s1 += __shfl_xor_sync(0xffffffffu, s1, o);
            s2 += __shfl_xor_sync(0xffffffffu, s2, o);
        }
        float mu = s1 * 0.015625f;
        float var = s2 * 0.015625f - mu * mu;
        float rs = rsqrtf(var + LNEPS);
        sln[warp * 64 + lane]      = (x0 - mu) * rs * lnsg[lane]      + lnsb[lane];
        sln[warp * 64 + lane + 32] = (x1 - mu) * rs * lnsg[lane + 32] + lnsb[lane + 32];
    }
    __syncthreads();
    for (int i = t; i < 512; i += 256) {
        int s = i >> 6, c = i & 63;
        float a = 0.f;
        #pragma unroll 8
        for (int d = 0; d < 64; d++) a += sln[s * 64 + d] * Wq[d * 64 + c];
        g_q[b * 512 + i] = a;
    }
}

// ---------------------------------------------------------------------------
// Attention: shuffle-free; k AND v staged through the same per-warp smem
// buffer (k dead after logits).
// smem: qT @0 (2048) | sKu [8][32*33] u32 @2048 (33792) |
//       sAb [8][256] f32 @35840 (8192) | wacc [8][520] @44032 (16640)
//       -> 60672 B (3 CTAs/SM)
// ---------------------------------------------------------------------------
#define ATTN_SMEM_BYTES 60672

__global__ __launch_bounds__(256) void attn_kernel()
{
    extern __shared__ char smc[];
    float* qT   = (float*)smc;              // [64][8]
    u32*   sKu  = (u32*)(smc + 2048);       // per-warp [32][33]
    float* sAb  = (float*)(smc + 35840);    // per-warp [32][8]
    float* wacc = (float*)(smc + 44032);    // [8][520]

    int b = blockIdx.x >> 6, pb = blockIdx.x & 63;
    int t = threadIdx.x, warp = t >> 5, lane = t & 31;

    for (int i = t; i < 512; i += 256) {
        int s = i >> 6, d = i & 63;
        qT[d * 8 + s] = g_q[b * 512 + i];
    }
    __syncthreads();

    size_t rowbase = (size_t)b * N_ + pb * 256 + warp * 32;
    const unsigned* kp = g_kh + rowbase * 32;
    const unsigned* vp = g_vh + rowbase * 32;

    // ---- stage k tile (raw bf16x2) ----
    u32* mk = sKu + warp * 1056;
    #pragma unroll 4
    for (int i = 0; i < 32; i++) mk[i * 33 + lane] = kp[i * 32 + lane];
    __syncwarp();

    // ---- logits for own row (row = lane) ----
    float lg[8];
    #pragma unroll
    for (int s = 0; s < 8; s++) lg[s] = 0.f;
    {
        const u32* myk = mk + lane * 33;
        #pragma unroll 8
        for (int j = 0; j < 32; j++) {
            float2 kf = u2f2(myk[j]);
            int d0 = j * 2;
            float4 qa = *(const float4*)(qT + d0 * 8);
            float4 qb = *(const float4*)(qT + d0 * 8 + 4);
            lg[0] += kf.x * qa.x; lg[1] += kf.x * qa.y;
            lg[2] += kf.x * qa.z; lg[3] += kf.x * qa.w;
            lg[4] += kf.x * qb.x; lg[5] += kf.x * qb.y;
            lg[6] += kf.x * qb.z; lg[7] += kf.x * qb.w;
            float4 qc = *(const float4*)(qT + d0 * 8 + 8);
            float4 qd = *(const float4*)(qT + d0 * 8 + 12);
            lg[0] += kf.y * qc.x; lg[1] += kf.y * qc.y;
            lg[2] += kf.y * qc.z; lg[3] += kf.y * qc.w;
            lg[4] += kf.y * qd.x; lg[5] += kf.y * qd.y;
            lg[6] += kf.y * qd.z; lg[7] += kf.y * qd.w;
        }
    }
    // ---- per-lane softmax over S=8, + eps ----
    float den8[8];
    {
        #pragma unroll
        for (int s = 0; s < 8; s++) lg[s] *= 0.125f;
        float mx = lg[0];
        #pragma unroll
        for (int s = 1; s < 8; s++) mx = fmaxf(mx, lg[s]);
        float se = 0.f;
        #pragma unroll
        for (int s = 0; s < 8; s++) { lg[s] = __expf(lg[s] - mx); se += lg[s]; }
        float inv = 1.f / se;
        #pragma unroll
        for (int s = 0; s < 8; s++) { lg[s] = lg[s] * inv + ATTN_EPS; den8[s] = lg[s]; }
        float* pa = sAb + warp * 256 + lane * 8;
        *(float4*)pa = make_float4(lg[0], lg[1], lg[2], lg[3]);
        *(float4*)(pa + 4) = make_float4(lg[4], lg[5], lg[6], lg[7]);
    }
    __syncwarp();   // all lanes done reading k from mk + sAb visible

    // ---- stage v tile into same buffer ----
    #pragma unroll 4
    for (int i = 0; i < 32; i++) mk[i * 33 + lane] = vp[i * 32 + lane];
    __syncwarp();

    // ---- accumulate numer[s][2 cols per lane] over the 32 rows ----
    float acc0[8], acc1[8];
    #pragma unroll
    for (int s = 0; s < 8; s++) { acc0[s] = 0.f; acc1[s] = 0.f; }
    {
        const float* pa = sAb + warp * 256;
        #pragma unroll 4
        for (int i = 0; i < 32; i++) {
            float2 v = u2f2(mk[i * 33 + lane]);
            float4 a0 = *(const float4*)(pa + i * 8);
            float4 a1 = *(const float4*)(pa + i * 8 + 4);
            acc0[0] += a0.x * v.x; acc1[0] += a0.x * v.y;
            acc0[1] += a0.y * v.x; acc1[1] += a0.y * v.y;
            acc0[2] += a0.z * v.x; acc1[2] += a0.z * v.y;
            acc0[3] += a0.w * v.x; acc1[3] += a0.w * v.y;
            acc0[4] += a1.x * v.x; acc1[4] += a1.x * v.y;
            acc0[5] += a1.y * v.x; acc1[5] += a1.y * v.y;
            acc0[6] += a1.z * v.x; acc1[6] += a1.z * v.y;
            acc0[7] += a1.w * v.x; acc1[7] += a1.w * v.y;
        }
    }
    #pragma unroll
    for (int s = 0; s < 8; s++) {
        float d = den8[s];
        #pragma unroll
        for (int o = 16; o; o >>= 1) d += __shfl_xor_sync(0xffffffffu, d, o);
        den8[s] = d;
    }

    float* wa = wacc + warp * 520;
    #pragma unroll
    for (int s = 0; s < 8; s++) {
        wa[s * 64 + lane * 2]     = acc0[s];
        wa[s * 64 + lane * 2 + 1] = acc1[s];
    }
    if (lane == 0) {
        #pragma unroll
        for (int s = 0; s < 8; s++) wa[512 + s] = den8[s];
    }
    __syncthreads();

    float* dst = g_part + (size_t)blockIdx.x * 520;
    for (int i = t; i < 520; i += 256) {
        float v = 0.f;
        #pragma unroll
        for (int w = 0; w < 8; w++) v += wacc[w * 520 + i];
        dst[i] = v;
    }
}

// ---------------------------------------------------------------------------
// Kernel: reduce partials -> updates -> GRU -> MLP residual (one block/b)
// ---------------------------------------------------------------------------
__global__ __launch_bounds__(256) void update_kernel(
    const float* __restrict__ W_ih, const float* __restrict__ W_hh,
    const float* __restrict__ b_ih, const float* __restrict__ b_hh,
    const float* __restrict__ lnmg, const float* __restrict__ lnmb,
    const float* __restrict__ mW1,  const float* __restrict__ mb1,
    const float* __restrict__ mW2,  const float* __restrict__ mb2,
    float* __restrict__ dout)
{
    __shared__ float red[520];
    __shared__ float u[512], prev[512], gx[1536], gh[1536];
    __shared__ float snew[512], sln[512], h1[1024];
    int b = blockIdx.x, t = threadIdx.x, warp = t >> 5, lane = t & 31;

    for (int i = t; i < 520; i += 256) {
        float v = 0.f;
        const float* p = g_part + (size_t)(b * 64) * 520 + i;
        #pragma unroll 8
        for (int pp = 0; pp < 64; pp++) v += p[pp * 520];
        red[i] = v;
    }
    for (int i = t; i < 512; i += 256) prev[i] = g_s[b * 512 + i];
    __syncthreads();

    for (int i = t; i < 512; i += 256) u[i] = red[i] / red[512 + (i >> 6)];
    __syncthreads();

    for (int i = t; i < 1536; i += 256) {
        int s = i / 192, j = i - s * 192;
        float ax = b_ih[j], ah = b_hh[j];
        const float* us = u + s * 64;
        const float* ps = prev + s * 64;
        #pragma unroll 8
        for (int d = 0; d < 64; d++) {
            ax += us[d] * W_ih[d * 192 + j];
            ah += ps[d] * W_hh[d * 192 + j];
        }
        gx[i] = ax; gh[i] = ah;
    }
    __syncthreads();

    for (int i = t; i < 512; i += 256) {
        int s = i >> 6, dd = i & 63;
        float xr = gx[s * 192 + dd], xz = gx[s * 192 + 64 + dd], xn = gx[s * 192 + 128 + dd];
        float hr = gh[s * 192 + dd], hz = gh[s * 192 + 64 + dd], hn = gh[s * 192 + 128 + dd];
        float r_ = 1.f / (1.f + __expf(-(xr + hr)));
        float z  = 1.f / (1.f + __expf(-(xz + hz)));
        float nn = tanhf(xn + r_ * hn);
        snew[i] = (1.f - z) * nn + z * prev[i];
    }
    __syncthreads();

    {
        const float* row = snew + warp * 64;
        float x0 = row[lane], x1 = row[lane + 32];
        float s1 = x0 + x1, s2 = x0 * x0 + x1 * x1;
        #pragma unroll
        for (int o = 16; o; o >>= 1) {
            s1 += __shfl_xor_sync(0xffffffffu, s1, o);
            s2 += __shfl_xor_sync(0xffffffffu, s2, o);
        }
        float mu = s1 * 0.015625f;
        float var = s2 * 0.015625f - mu * mu;
        float rs = rsqrtf(var + LNEPS);
        sln[warp * 64 + lane]      = (x0 - mu) * rs * lnmg[lane]      + lnmb[lane];
        sln[warp * 64 + lane + 32] = (x1 - mu) * rs * lnmg[lane + 32] + lnmb[lane + 32];
    }
    __syncthreads();

    for (int i = t; i < 1024; i += 256) {
        int s = i >> 7, j = i & 127;
        float a = mb1[j];
        const float* r = sln + s * 64;
        #pragma unroll 8
        for (int d = 0; d < 64; d++) a += r[d] * mW1[d * 128 + j];
        h1[i] = fmaxf(a, 0.f);
    }
    __syncthreads();

    for (int i = t; i < 512; i += 256) {
        int s = i >> 6, c = i & 63;
        float a = mb2[c];
        const float* r = h1 + s * 128;
        #pragma unroll 8
        for (int k = 0; k < 128; k++) a += r[k] * mW2[k * 64 + c];
        float val = snew[i] + a;
        g_s[b * 512 + i] = val;
        dout[b * 512 + i] = val;
    }
}

// ---------------------------------------------------------------------------
extern "C" void kernel_launch(void* const* d_in, const int* in_sizes, int n_in,
                              void* d_out, int out_size)
{
    (void)in_sizes; (void)n_in; (void)out_size;
    const float* inputs  = (const float*)d_in[0];
    const float* slots   = (const float*)d_in[1];
    const float* ln_in_g = (const float*)d_in[2];
    const float* ln_in_b = (const float*)d_in[3];
    const float* ln_s_g  = (const float*)d_in[4];
    const float* ln_s_b  = (const float*)d_in[5];
    const float* ln_m_g  = (const float*)d_in[6];
    const float* ln_m_b  = (const float*)d_in[7];
    const float* Wq      = (const float*)d_in[8];
    const float* Wk      = (const float*)d_in[9];
    const float* Wv      = (const float*)d_in[10];
    const float* W_ih    = (const float*)d_in[11];
    const float* W_hh    = (const float*)d_in[12];
    const float* b_ih    = (const float*)d_in[13];
    const float* b_hh    = (const float*)d_in[14];
    const float* mlp_W1  = (const float*)d_in[15];
    const float* mlp_b1  = (const float*)d_in[16];
    const float* mlp_W2  = (const float*)d_in[17];
    const float* mlp_b2  = (const float*)d_in[18];
    const float* pa_W    = (const float*)d_in[19];
    const float* pa_b    = (const float*)d_in[20];
    const float* pe_g    = (const float*)d_in[21];
    const float* pe_b    = (const float*)d_in[22];
    const float* pe_W1   = (const float*)d_in[23];
    const float* pe_b1   = (const float*)d_in[24];
    const float* pe_W2   = (const float*)d_in[25];
    const float* pe_b2   = (const float*)d_in[26];
    float* out = (float*)d_out;

    static int configured = 0;
    if (!configured) {
        cudaFuncSetAttribute(phaseA_kernel,
                             cudaFuncAttributeMaxDynamicSharedMemorySize, PA_SMEM_BYTES);
        cudaFuncSetAttribute(phaseB_kernel,
                             cudaFuncAttributeMaxDynamicSharedMemorySize, PB_SMEM_BYTES);
        cudaFuncSetAttribute(attn_kernel,
                             cudaFuncAttributeMaxDynamicSharedMemorySize, ATTN_SMEM_BYTES);
        configured = 1;
    }

    phaseA_kernel<<<2048, 256, PA_SMEM_BYTES>>>(
        inputs, ln_in_g, ln_in_b, Wk, Wv, pa_W, pa_b, pe_g, pe_b);

    phaseB_kernel<<<4096, 256, PB_SMEM_BYTES>>>(pe_W1, pe_b1, pe_W2, pe_b2);

    init_slots_kernel<<<32, 512>>>(slots);

    for (int it = 0; it < 3; it++) {
        slotq_kernel<<<32, 256>>>(ln_s_g, ln_s_b, Wq);
        attn_kernel<<<2048, 256, ATTN_SMEM_BYTES>>>();
        update_kernel<<<32, 256>>>(W_ih, W_hh, b_ih, b_hh,
                                   ln_m_g, ln_m_b,
                                   mlp_W1, mlp_b1, mlp_W2, mlp_b2, out);
    }
}

// round 11
// speedup vs baseline: 1.2211x; 1.2211x over previous
#include <cuda_runtime.h>
#include <cuda_bf16.h>
#include <cmath>

#define B_ 32
#define N_ 16384
#define D_ 64
#define S_ 8
#define H_ 128
#define LNEPS 1e-5f
#define ATTN_EPS 1e-8f

typedef unsigned long long ull;
typedef unsigned int u32;

// ---------------- scratch (device globals; no allocations allowed) ----------
__device__ unsigned g_kh[B_ * N_ * 32];   // k_pos bf16x2 (64 MB)
__device__ unsigned g_vh[B_ * N_ * 32];   // v_pos bf16x2 (64 MB)
__device__ float g_q[B_ * S_ * D_];
__device__ float g_s[B_ * S_ * D_];
__device__ float g_part[B_ * 64 * 520];   // per-(b, partial-block) numer(512)+den(8)

// ---------------- helpers ----------------------------------------------------
__device__ __forceinline__ unsigned bf2u(float a, float b) {
    __nv_bfloat162 h = __float22bfloat162_rn(make_float2(a, b));
    return *(unsigned*)&h;
}
__device__ __forceinline__ float2 u2f2(unsigned u) {
    __nv_bfloat162 h = *(__nv_bfloat162*)&u;
    return __bfloat1622float2(h);
}
__device__ __forceinline__ void ldsm_x4(u32 a[4], u32 addr) {
    asm volatile("ldmatrix.sync.aligned.m8n8.x4.shared.b16 {%0,%1,%2,%3}, [%4];"
                 : "=r"(a[0]), "=r"(a[1]), "=r"(a[2]), "=r"(a[3]) : "r"(addr));
}
__device__ __forceinline__ void ldsm_x2t(u32 b[2], u32 addr) {
    asm volatile("ldmatrix.sync.aligned.m8n8.x2.trans.shared.b16 {%0,%1}, [%2];"
                 : "=r"(b[0]), "=r"(b[1]) : "r"(addr));
}
__device__ __forceinline__ void mma_bf16(float d[4], const u32 a[4], const u32 b[2]) {
    asm volatile("mma.sync.aligned.m16n8k16.row.col.f32.bf16.bf16.f32 "
                 "{%0,%1,%2,%3},{%4,%5,%6,%7},{%8,%9},{%0,%1,%2,%3};"
                 : "+f"(d[0]), "+f"(d[1]), "+f"(d[2]), "+f"(d[3])
                 : "r"(a[0]), "r"(a[1]), "r"(a[2]), "r"(a[3]), "r"(b[0]), "r"(b[1]));
}

// ---------------------------------------------------------------------------
// Kernel 1: fused preprocessing (R9 version, known-good). bf16 HMMA, two
// passes (k then v) per tile; smem 93184 B -> 2 CTAs/SM.
// ---------------------------------------------------------------------------
#define PRE_SMEM_BYTES 93184

__global__ __launch_bounds__(256, 2) void preprocess_kernel(
    const float* __restrict__ inp,
    const float* __restrict__ lng, const float* __restrict__ lnb,
    const float* __restrict__ Wk,  const float* __restrict__ Wv,
    const float* __restrict__ paW, const float* __restrict__ pab,
    const float* __restrict__ peg, const float* __restrict__ peb,
    const float* __restrict__ W1,  const float* __restrict__ b1,
    const float* __restrict__ W2,  const float* __restrict__ b2)
{
    extern __shared__ char smem[];
    __nv_bfloat16* sWk = (__nv_bfloat16*)(smem);
    __nv_bfloat16* sWv = (__nv_bfloat16*)(smem + 9216);
    __nv_bfloat16* sW1 = (__nv_bfloat16*)(smem + 18432);
    __nv_bfloat16* sW2 = (__nv_bfloat16*)(smem + 35840);
    __nv_bfloat16* sX  = (__nv_bfloat16*)(smem + 54272);
    float*         sTf = (float*)(smem + 63488);          // aliased with sHb
    __nv_bfloat16* sHb = (__nv_bfloat16*)(smem + 63488);
    __nv_bfloat16* sTb = (__nv_bfloat16*)(smem + 80896);
    float*         sV  = (float*)(smem + 90112);
    float*         sG  = (float*)(smem + 92672);

    u32 sb = (u32)__cvta_generic_to_shared(smem);
    const u32 sbWk = sb, sbWv = sb + 9216, sbW1 = sb + 18432, sbW2 = sb + 35840;
    const u32 sbX = sb + 54272, sbHb = sb + 63488, sbTb = sb + 80896;

    const int t = threadIdx.x, warp = t >> 5, lane = t & 31;
    const int mt = warp >> 1, ng = warp & 1;
    const int l15 = lane & 15, lh = lane >> 4, lr = lane >> 2, lc = (lane & 3) * 2;

    for (int i = t; i < 4096; i += 256) {
        int r = i >> 6, c = i & 63;
        sWk[r * 72 + c] = __float2bfloat16(Wk[i]);
        sWv[r * 72 + c] = __float2bfloat16(Wv[i]);
    }
    for (int i = t; i < 8192; i += 256) {
        int r1_ = i >> 7, c1_ = i & 127;
        sW1[r1_ * 136 + c1_] = __float2bfloat16(W1[i]);
        int r2_ = i >> 6, c2_ = i & 63;
        sW2[r2_ * 72 + c2_] = __float2bfloat16(W2[i]);
    }
    if (t < 64) {
        sV[t]       = paW[t];
        sV[64 + t]  = paW[64 + t];
        sV[128 + t] = pab[t];
        sV[192 + t] = lng[t];
        sV[256 + t] = lnb[t];
        sV[320 + t] = peg[t];
        sV[384 + t] = peb[t];
        sV[576 + t] = b2[t];
    }
    if (t < 128) sV[448 + t] = b1[t];
    __syncthreads();

    const float *pa0 = sV, *pa1 = sV + 64, *pbv = sV + 128,
                *sing = sV + 192, *sinb = sV + 256,
                *speg = sV + 320, *speb = sV + 384,
                *sb1 = sV + 448, *sb2v = sV + 576;

    for (int ti = 0; ti < 4; ti++) {
        int tile = blockIdx.x * 4 + ti;          // 8192 tiles of 64 rows
        int rowbase = tile * 64;

        for (int rr = warp; rr < 64; rr += 8) {
            const float* rp = inp + (size_t)(rowbase + rr) * 66;
            float x0 = rp[lane], x1 = rp[lane + 32];
            float s1 = x0 + x1, s2 = x0 * x0 + x1 * x1;
            #pragma unroll
            for (int o = 16; o; o >>= 1) {
                s1 += __shfl_xor_sync(0xffffffffu, s1, o);
                s2 += __shfl_xor_sync(0xffffffffu, s2, o);
            }
            float mu = s1 * 0.015625f;
            float var = s2 * 0.015625f - mu * mu;
            float rs = rsqrtf(var + LNEPS);
            sX[rr * 72 + lane]      = __float2bfloat16((x0 - mu) * rs * sing[lane]      + sinb[lane]);
            sX[rr * 72 + lane + 32] = __float2bfloat16((x1 - mu) * rs * sing[lane + 32] + sinb[lane + 32]);
            if (lane < 2) sG[rr * 2 + lane] = rp[64 + lane];
        }
        __syncthreads();

        #pragma unroll 1
        for (int pass = 0; pass < 2; pass++) {
            const u32 sbW = pass ? sbWv : sbWk;
            unsigned* outg = pass ? g_vh : g_kh;

            {
                float acc[4][4];
                #pragma unroll
                for (int s = 0; s < 4; s++)
                    #pragma unroll
                    for (int j = 0; j < 4; j++) acc[s][j] = 0.f;

                #pragma unroll
                for (int ks = 0; ks < 4; ks++) {
                    u32 a[4];
                    ldsm_x4(a, sbX + ((mt * 16 + l15) * 72 + ks * 16 + lh * 8) * 2);
                    #pragma unroll
                    for (int s = 0; s < 4; s++) {
                        u32 b[2];
                        int nb = ng * 32 + s * 8;
                        ldsm_x2t(b, sbW + ((ks * 16 + l15) * 72 + nb) * 2);
                        mma_bf16(acc[s], a, b);
                    }
                }
                int r0 = mt * 16 + lr, r1 = r0 + 8;
                float gx0 = sG[r0 * 2], gy0 = sG[r0 * 2 + 1];
                float gx1 = sG[r1 * 2], gy1 = sG[r1 * 2 + 1];
                #pragma unroll
                for (int s = 0; s < 4; s++) {
                    int c = ng * 32 + s * 8 + lc;
                    float p0a = pa0[c], p0b = pa0[c + 1];
                    float p1a = pa1[c], p1b = pa1[c + 1];
                    float pba = pbv[c], pbb = pbv[c + 1];
                    *(float2*)&sTf[r0 * 66 + c] =
                        make_float2(acc[s][0] + gx0 * p0a + gy0 * p1a + pba,
                                    acc[s][1] + gx0 * p0b + gy0 * p1b + pbb);
                    *(float2*)&sTf[r1 * 66 + c] =
                        make_float2(acc[s][2] + gx1 * p0a + gy1 * p1a + pba,
                                    acc[s][3] + gx1 * p0b + gy1 * p1b + pbb);
                }
            }
            __syncthreads();

            for (int rr = warp; rr < 64; rr += 8) {
                float x0 = sTf[rr * 66 + lane], x1 = sTf[rr * 66 + lane + 32];
                float s1 = x0 + x1, s2 = x0 * x0 + x1 * x1;
                #pragma unroll
                for (int o = 16; o; o >>= 1) {
                    s1 += __shfl_xor_sync(0xffffffffu, s1, o);
                    s2 += __shfl_xor_sync(0xffffffffu, s2, o);
                }
                float mu = s1 * 0.015625f;
                float var = s2 * 0.015625f - mu * mu;
                float rs = rsqrtf(var + LNEPS);
                sTb[rr * 72 + lane]      = __float2bfloat16((x0 - mu) * rs * speg[lane]      + speb[lane]);
                sTb[rr * 72 + lane + 32] = __float2bfloat16((x1 - mu) * rs * speg[lane + 32] + speb[lane + 32]);
            }
            __syncthreads();

            {
                float acc[8][4];
                #pragma unroll
                for (int s = 0; s < 8; s++)
                    #pragma unroll
                    for (int j = 0; j < 4; j++) acc[s][j] = 0.f;

                #pragma unroll
                for (int ks = 0; ks < 4; ks++) {
                    u32 a[4];
                    ldsm_x4(a, sbTb + ((mt * 16 + l15) * 72 + ks * 16 + lh * 8) * 2);
                    #pragma unroll
                    for (int s = 0; s < 8; s++) {
                        u32 b[2];
                        int nb = ng * 64 + s * 8;
                        ldsm_x2t(b, sbW1 + ((ks * 16 + l15) * 136 + nb) * 2);
                        mma_bf16(acc[s], a, b);
                    }
                }
                __syncthreads();   // Tf reads done before H overwrite (alias safety)
                int r0 = mt * 16 + lr, r1 = r0 + 8;
                #pragma unroll
                for (int s = 0; s < 8; s++) {
                    int c = ng * 64 + s * 8 + lc;
                    float ba = sb1[c], bb = sb1[c + 1];
                    *(u32*)&sHb[r0 * 136 + c] =
                        bf2u(fmaxf(acc[s][0] + ba, 0.f), fmaxf(acc[s][1] + bb, 0.f));
                    *(u32*)&sHb[r1 * 136 + c] =
                        bf2u(fmaxf(acc[s][2] + ba, 0.f), fmaxf(acc[s][3] + bb, 0.f));
                }
            }
            __syncthreads();

            {
                float acc[4][4];
                #pragma unroll
                for (int s = 0; s < 4; s++)
                    #pragma unroll
                    for (int j = 0; j < 4; j++) acc[s][j] = 0.f;

                #pragma unroll
                for (int ks = 0; ks < 8; ks++) {
                    u32 a[4];
                    ldsm_x4(a, sbHb + ((mt * 16 + l15) * 136 + ks * 16 + lh * 8) * 2);
                    #pragma unroll
                    for (int s = 0; s < 4; s++) {
                        u32 b[2];
                        int nb = ng * 32 + s * 8;
                        ldsm_x2t(b, sbW2 + ((ks * 16 + l15) * 72 + nb) * 2);
                        mma_bf16(acc[s], a, b);
                    }
                }
                int r0 = mt * 16 + lr, r1 = r0 + 8;
                #pragma unroll
                for (int s = 0; s < 4; s++) {
                    int c = ng * 32 + s * 8 + lc;
                    float ba = sb2v[c], bb = sb2v[c + 1];
                    outg[(size_t)(rowbase + r0) * 32 + (c >> 1)] =
                        bf2u(acc[s][0] + ba, acc[s][1] + bb);
                    outg[(size_t)(rowbase + r1) * 32 + (c >> 1)] =
                        bf2u(acc[s][2] + ba, acc[s][3] + bb);
                }
            }
            __syncthreads();
        }
    }
}

// ---------------------------------------------------------------------------
// initq: s = broadcast(slots); q = LN(s; ln_s) @ Wq  (one block per b)
// ---------------------------------------------------------------------------
__global__ __launch_bounds__(256) void initq_kernel(
    const float* __restrict__ slots,
    const float* __restrict__ lnsg, const float* __restrict__ lnsb,
    const float* __restrict__ Wq)
{
    __shared__ float ss[512], sln[512];
    int b = blockIdx.x, t = threadIdx.x, warp = t >> 5, lane = t & 31;
    for (int i = t; i < 512; i += 256) {
        float v = slots[i];
        g_s[b * 512 + i] = v;
        ss[i] = v;
    }
    __syncthreads();
    {
        const float* row = ss + warp * 64;
        float x0 = row[lane], x1 = row[lane + 32];
        float s1 = x0 + x1, s2 = x0 * x0 + x1 * x1;
        #pragma unroll
        for (int o = 16; o; o >>= 1) {
            s1 += __shfl_xor_sync(0xffffffffu, s1, o);
            s2 += __shfl_xor_sync(0xffffffffu, s2, o);
        }
        float mu = s1 * 0.015625f;
        float var = s2 * 0.015625f - mu * mu;
        float rs = rsqrtf(var + LNEPS);
        sln[warp * 64 + lane]      = (x0 - mu) * rs * lnsg[lane]      + lnsb[lane];
        sln[warp * 64 + lane + 32] = (x1 - mu) * rs * lnsg[lane + 32] + lnsb[lane + 32];
    }
    __syncthreads();
    for (int i = t; i < 512; i += 256) {
        int s = i >> 6, c = i & 63;
        float a = 0.f;
        #pragma unroll 8
        for (int d = 0; d < 64; d++) a += sln[s * 64 + d] * Wq[d * 64 + c];
        g_q[b * 512 + i] = a;
    }
}

// ---------------------------------------------------------------------------
// Attention: HMMA logits + quad-shuffle softmax + scalar v-accum.
// smem: qTb bf16[64][8] @0 (1024) | sKu u32 per-warp [32][36] @1024 (36864) |
//       sAb f32 per-warp [32][8] @37888 (8192) | wacc [8][520] @46080 (16640)
//       -> 62720 B (3 CTAs/SM)
// ---------------------------------------------------------------------------
#define ATTN_SMEM_BYTES 62720

__global__ __launch_bounds__(256) void attn_kernel()
{
    extern __shared__ char smc[];
    __nv_bfloat16* qTb = (__nv_bfloat16*)smc;     // [64][8]
    u32*   sKu  = (u32*)(smc + 1024);             // per-warp [32][36]
    float* sAb  = (float*)(smc + 37888);          // per-warp [32][8]
    float* wacc = (float*)(smc + 46080);          // [8][520]

    u32 sb = (u32)__cvta_generic_to_shared(smc);
    const u32 sbQ = sb, sbK = sb + 1024;

    int b = blockIdx.x >> 6, pb = blockIdx.x & 63;
    int t = threadIdx.x, warp = t >> 5, lane = t & 31;
    const int l15 = lane & 15, lh = lane >> 4;
    const int q = lane >> 2, c0 = (lane & 3) * 2;

    // build qTb[d][s] bf16
    for (int i = t; i < 512; i += 256) {
        int s = i >> 6, d = i & 63;
        qTb[d * 8 + s] = __float2bfloat16(g_q[b * 512 + i]);
    }
    __syncthreads();

    // Q fragments (constant for the block)
    u32 qf[4][2];
    #pragma unroll
    for (int kc = 0; kc < 4; kc++)
        ldsm_x2t(qf[kc], sbQ + ((kc * 16 + l15) * 8) * 2);

    size_t rowbase = (size_t)b * N_ + pb * 256 + warp * 32;
    const unsigned* kp = g_kh + rowbase * 32;
    const unsigned* vp = g_vh + rowbase * 32;

    // stage k tile (raw bf16x2, stride 36 u32 = 72 bf16)
    u32* mk = sKu + warp * 1152;
    const u32 wbase = sbK + warp * 4608;
    #pragma unroll 4
    for (int i = 0; i < 32; i++) mk[i * 36 + lane] = kp[i * 32 + lane];
    __syncwarp();

    // logits via HMMA: L[32x8] = K[32x64] @ Q^T
    float acc[2][4];
    #pragma unroll
    for (int m = 0; m < 2; m++)
        #pragma unroll
        for (int j = 0; j < 4; j++) acc[m][j] = 0.f;
    #pragma unroll
    for (int m = 0; m < 2; m++) {
        #pragma unroll
        for (int kc = 0; kc < 4; kc++) {
            u32 a[4];
            ldsm_x4(a, wbase + ((m * 16 + l15) * 72 + kc * 16 + lh * 8) * 2);
            mma_bf16(acc[m], a, qf[kc]);
        }
    }

    // softmax over S=8 per row (row's 8 logits live in one quad)
    float den0 = 0.f, den1 = 0.f;
    float* paw = sAb + warp * 256;
    #pragma unroll
    for (int m = 0; m < 2; m++) {
        #pragma unroll
        for (int h = 0; h < 2; h++) {
            float e0 = acc[m][h * 2]     * 0.125f;
            float e1 = acc[m][h * 2 + 1] * 0.125f;
            float mx = fmaxf(e0, e1);
            mx = fmaxf(mx, __shfl_xor_sync(0xffffffffu, mx, 1));
            mx = fmaxf(mx, __shfl_xor_sync(0xffffffffu, mx, 2));
            e0 = __expf(e0 - mx); e1 = __expf(e1 - mx);
            float se = e0 + e1;
            se += __shfl_xor_sync(0xffffffffu, se, 1);
            se += __shfl_xor_sync(0xffffffffu, se, 2);
            float inv = 1.f / se;
            e0 = e0 * inv + ATTN_EPS;
            e1 = e1 * inv + ATTN_EPS;
            int row = m * 16 + h * 8 + q;
            paw[row * 8 + c0]     = e0;
            paw[row * 8 + c0 + 1] = e1;
            den0 += e0; den1 += e1;
        }
    }
    // per-slot denominators: reduce over lanes with same (lane&3)
    den0 += __shfl_xor_sync(0xffffffffu, den0, 4);
    den0 += __shfl_xor_sync(0xffffffffu, den0, 8);
    den0 += __shfl_xor_sync(0xffffffffu, den0, 16);
    den1 += __shfl_xor_sync(0xffffffffu, den1, 4);
    den1 += __shfl_xor_sync(0xffffffffu, den1, 8);
    den1 += __shfl_xor_sync(0xffffffffu, den1, 16);
    __syncwarp();

    // stage v into same buffer (k dead)
    #pragma unroll 4
    for (int i = 0; i < 32; i++) mk[i * 36 + lane] = vp[i * 32 + lane];
    __syncwarp();

    // numer[s][2 cols per lane] over the 32 rows
    float acc0[8], acc1[8];
    #pragma unroll
    for (int s = 0; s < 8; s++) { acc0[s] = 0.f; acc1[s] = 0.f; }
    #pragma unroll 4
    for (int i = 0; i < 32; i++) {
        float2 v = u2f2(mk[i * 36 + lane]);
        float4 a0 = *(const float4*)(paw + i * 8);
        float4 a1 = *(const float4*)(paw + i * 8 + 4);
        acc0[0] += a0.x * v.x; acc1[0] += a0.x * v.y;
        acc0[1] += a0.y * v.x; acc1[1] += a0.y * v.y;
        acc0[2] += a0.z * v.x; acc1[2] += a0.z * v.y;
        acc0[3] += a0.w * v.x; acc1[3] += a0.w * v.y;
        acc0[4] += a1.x * v.x; acc1[4] += a1.x * v.y;
        acc0[5] += a1.y * v.x; acc1[5] += a1.y * v.y;
        acc0[6] += a1.z * v.x; acc1[6] += a1.z * v.y;
        acc0[7] += a1.w * v.x; acc1[7] += a1.w * v.y;
    }

    float* wa = wacc + warp * 520;
    #pragma unroll
    for (int s = 0; s < 8; s++) {
        wa[s * 64 + lane * 2]     = acc0[s];
        wa[s * 64 + lane * 2 + 1] = acc1[s];
    }
    if (lane < 4) {
        wa[512 + c0]     = den0;
        wa[512 + c0 + 1] = den1;
    }
    __syncthreads();

    float* dst = g_part + (size_t)blockIdx.x * 520;
    for (int i = t; i < 520; i += 256) {
        float v = 0.f;
        #pragma unroll
        for (int w = 0; w < 8; w++) v += wacc[w * 520 + i];
        dst[i] = v;
    }
}

// ---------------------------------------------------------------------------
// update: reduce partials -> GRU -> MLP residual -> NEXT q (fused slotq)
// ---------------------------------------------------------------------------
__global__ __launch_bounds__(256) void update_kernel(
    const float* __restrict__ W_ih, const float* __restrict__ W_hh,
    const float* __restrict__ b_ih, const float* __restrict__ b_hh,
    const float* __restrict__ lnmg, const float* __restrict__ lnmb,
    const float* __restrict__ mW1,  const float* __restrict__ mb1,
    const float* __restrict__ mW2,  const float* __restrict__ mb2,
    const float* __restrict__ lnsg, const float* __restrict__ lnsb,
    const float* __restrict__ Wq,
    float* __restrict__ dout)
{
    __shared__ float red[520];
    __shared__ float u[512], prev[512], gx[1536], gh[1536];
    __shared__ float snew[512], sln[512], h1[1024];
    int b = blockIdx.x, t = threadIdx.x, warp = t >> 5, lane = t & 31;

    for (int i = t; i < 520; i += 256) {
        float v = 0.f;
        const float* p = g_part + (size_t)(b * 64) * 520 + i;
        #pragma unroll 8
        for (int pp = 0; pp < 64; pp++) v += p[pp * 520];
        red[i] = v;
    }
    for (int i = t; i < 512; i += 256) prev[i] = g_s[b * 512 + i];
    __syncthreads();

    for (int i = t; i < 512; i += 256) u[i] = red[i] / red[512 + (i >> 6)];
    __syncthreads();

    for (int i = t; i < 1536; i += 256) {
        int s = i / 192, j = i - s * 192;
        float ax = b_ih[j], ah = b_hh[j];
        const float* us = u + s * 64;
        const float* ps = prev + s * 64;
        #pragma unroll 8
        for (int d = 0; d < 64; d++) {
            ax += us[d] * W_ih[d * 192 + j];
            ah += ps[d] * W_hh[d * 192 + j];
        }
        gx[i] = ax; gh[i] = ah;
    }
    __syncthreads();

    for (int i = t; i < 512; i += 256) {
        int s = i >> 6, dd = i & 63;
        float xr = gx[s * 192 + dd], xz = gx[s * 192 + 64 + dd], xn = gx[s * 192 + 128 + dd];
        float hr = gh[s * 192 + dd], hz = gh[s * 192 + 64 + dd], hn = gh[s * 192 + 128 + dd];
        float r_ = 1.f / (1.f + __expf(-(xr + hr)));
        float z  = 1.f / (1.f + __expf(-(xz + hz)));
        float nn = tanhf(xn + r_ * hn);
        snew[i] = (1.f - z) * nn + z * prev[i];
    }
    __syncthreads();

    {
        const float* row = snew + warp * 64;
        float x0 = row[lane], x1 = row[lane + 32];
        float s1 = x0 + x1, s2 = x0 * x0 + x1 * x1;
        #pragma unroll
        for (int o = 16; o; o >>= 1) {
            s1 += __shfl_xor_sync(0xffffffffu, s1, o);
            s2 += __shfl_xor_sync(0xffffffffu, s2, o);
        }
        float mu = s1 * 0.015625f;
        float var = s2 * 0.015625f - mu * mu;
        float rs = rsqrtf(var + LNEPS);
        sln[warp * 64 + lane]      = (x0 - mu) * rs * lnmg[lane]      + lnmb[lane];
        sln[warp * 64 + lane + 32] = (x1 - mu) * rs * lnmg[lane + 32] + lnmb[lane + 32];
    }
    __syncthreads();

    for (int i = t; i < 1024; i += 256) {
        int s = i >> 7, j = i & 127;
        float a = mb1[j];
        const float* r = sln + s * 64;
        #pragma unroll 8
        for (int d = 0; d < 64; d++) a += r[d] * mW1[d * 128 + j];
        h1[i] = fmaxf(a, 0.f);
    }
    __syncthreads();

    for (int i = t; i < 512; i += 256) {
        int s = i >> 6, c = i & 63;
        float a = mb2[c];
        const float* r = h1 + s * 128;
        #pragma unroll 8
        for (int k = 0; k < 128; k++) a += r[k] * mW2[k * 64 + c];
        float val = snew[i] + a;
        g_s[b * 512 + i] = val;
        dout[b * 512 + i] = val;
        u[i] = val;             // reuse buffer for next-q computation
    }
    __syncthreads();

    // ---- fused slotq: q = LN(s_new; ln_s) @ Wq ----
    {
        const float* row = u + warp * 64;
        float x0 = row[lane], x1 = row[lane + 32];
        float s1 = x0 + x1, s2 = x0 * x0 + x1 * x1;
        #pragma unroll
        for (int o = 16; o; o >>= 1) {
            s1 += __shfl_xor_sync(0xffffffffu, s1, o);
            s2 += __shfl_xor_sync(0xffffffffu, s2, o);
        }
        float mu = s1 * 0.015625f;
        float var = s2 * 0.015625f - mu * mu;
        float rs = rsqrtf(var + LNEPS);
        sln[warp * 64 + lane]      = (x0 - mu) * rs * lnsg[lane]      + lnsb[lane];
        sln[warp * 64 + lane + 32] = (x1 - mu) * rs * lnsg[lane + 32] + lnsb[lane + 32];
    }
    __syncthreads();
    for (int i = t; i < 512; i += 256) {
        int s = i >> 6, c = i & 63;
        float a = 0.f;
        #pragma unroll 8
        for (int d = 0; d < 64; d++) a += sln[s * 64 + d] * Wq[d * 64 + c];
        g_q[b * 512 + i] = a;
    }
}

// ---------------------------------------------------------------------------
extern "C" void kernel_launch(void* const* d_in, const int* in_sizes, int n_in,
                              void* d_out, int out_size)
{
    (void)in_sizes; (void)n_in; (void)out_size;
    const float* inputs  = (const float*)d_in[0];
    const float* slots   = (const float*)d_in[1];
    const float* ln_in_g = (const float*)d_in[2];
    const float* ln_in_b = (const float*)d_in[3];
    const float* ln_s_g  = (const float*)d_in[4];
    const float* ln_s_b  = (const float*)d_in[5];
    const float* ln_m_g  = (const float*)d_in[6];
    const float* ln_m_b  = (const float*)d_in[7];
    const float* Wq      = (const float*)d_in[8];
    const float* Wk      = (const float*)d_in[9];
    const float* Wv      = (const float*)d_in[10];
    const float* W_ih    = (const float*)d_in[11];
    const float* W_hh    = (const float*)d_in[12];
    const float* b_ih    = (const float*)d_in[13];
    const float* b_hh    = (const float*)d_in[14];
    const float* mlp_W1  = (const float*)d_in[15];
    const float* mlp_b1  = (const float*)d_in[16];
    const float* mlp_W2  = (const float*)d_in[17];
    const float* mlp_b2  = (const float*)d_in[18];
    const float* pa_W    = (const float*)d_in[19];
    const float* pa_b    = (const float*)d_in[20];
    const float* pe_g    = (const float*)d_in[21];
    const float* pe_b    = (const float*)d_in[22];
    const float* pe_W1   = (const float*)d_in[23];
    const float* pe_b1   = (const float*)d_in[24];
    const float* pe_W2   = (const float*)d_in[25];
    const float* pe_b2   = (const float*)d_in[26];
    float* out = (float*)d_out;

    static int configured = 0;
    if (!configured) {
        cudaFuncSetAttribute(preprocess_kernel,
                             cudaFuncAttributeMaxDynamicSharedMemorySize, PRE_SMEM_BYTES);
        cudaFuncSetAttribute(attn_kernel,
                             cudaFuncAttributeMaxDynamicSharedMemorySize, ATTN_SMEM_BYTES);
        configured = 1;
    }

    preprocess_kernel<<<2048, 256, PRE_SMEM_BYTES>>>(
        inputs, ln_in_g, ln_in_b, Wk, Wv, pa_W, pa_b, pe_g, pe_b,
        pe_W1, pe_b1, pe_W2, pe_b2);

    initq_kernel<<<32, 256>>>(slots, ln_s_g, ln_s_b, Wq);

    for (int it = 0; it < 3; it++) {
        attn_kernel<<<2048, 256, ATTN_SMEM_BYTES>>>();
        update_kernel<<<32, 256>>>(W_ih, W_hh, b_ih, b_hh,
                                   ln_m_g, ln_m_b,
                                   mlp_W1, mlp_b1, mlp_W2, mlp_b2,
                                   ln_s_g, ln_s_b, Wq, out);
    }
}

// round 12
// speedup vs baseline: 1.4180x; 1.1613x over previous
#include <cuda_runtime.h>
#include <cuda_bf16.h>
#include <cmath>

#define B_ 32
#define N_ 16384
#define D_ 64
#define S_ 8
#define H_ 128
#define LNEPS 1e-5f
#define ATTN_EPS 1e-8f

typedef unsigned long long ull;
typedef unsigned int u32;

// ---------------- scratch (device globals; no allocations allowed) ----------
__device__ unsigned g_kh[B_ * N_ * 32];   // k_pos bf16x2 (64 MB)
__device__ unsigned g_vh[B_ * N_ * 32];   // v_pos bf16x2 (64 MB)
__device__ float g_q[B_ * S_ * D_];
__device__ float g_s[B_ * S_ * D_];
__device__ float g_part[B_ * 64 * 520];   // per-(b, partial-block) numer(512)+den(8)

// ---------------- helpers ----------------------------------------------------
__device__ __forceinline__ unsigned bf2u(float a, float b) {
    __nv_bfloat162 h = __float22bfloat162_rn(make_float2(a, b));
    return *(unsigned*)&h;
}
__device__ __forceinline__ float2 u2f2(unsigned u) {
    __nv_bfloat162 h = *(__nv_bfloat162*)&u;
    return __bfloat1622float2(h);
}
__device__ __forceinline__ void ldsm_x4(u32 a[4], u32 addr) {
    asm volatile("ldmatrix.sync.aligned.m8n8.x4.shared.b16 {%0,%1,%2,%3}, [%4];"
                 : "=r"(a[0]), "=r"(a[1]), "=r"(a[2]), "=r"(a[3]) : "r"(addr));
}
__device__ __forceinline__ void ldsm_x2t(u32 b[2], u32 addr) {
    asm volatile("ldmatrix.sync.aligned.m8n8.x2.trans.shared.b16 {%0,%1}, [%2];"
                 : "=r"(b[0]), "=r"(b[1]) : "r"(addr));
}
__device__ __forceinline__ void mma_bf16(float d[4], const u32 a[4], const u32 b[2]) {
    asm volatile("mma.sync.aligned.m16n8k16.row.col.f32.bf16.bf16.f32 "
                 "{%0,%1,%2,%3},{%4,%5,%6,%7},{%8,%9},{%0,%1,%2,%3};"
                 : "+f"(d[0]), "+f"(d[1]), "+f"(d[2]), "+f"(d[3])
                 : "r"(a[0]), "r"(a[1]), "r"(a[2]), "r"(a[3]), "r"(b[0]), "r"(b[1]));
}

// ---------------------------------------------------------------------------
// Kernel 1: fused preprocessing (unchanged from R11 best).
// ---------------------------------------------------------------------------
#define PRE_SMEM_BYTES 93184

__global__ __launch_bounds__(256, 2) void preprocess_kernel(
    const float* __restrict__ inp,
    const float* __restrict__ lng, const float* __restrict__ lnb,
    const float* __restrict__ Wk,  const float* __restrict__ Wv,
    const float* __restrict__ paW, const float* __restrict__ pab,
    const float* __restrict__ peg, const float* __restrict__ peb,
    const float* __restrict__ W1,  const float* __restrict__ b1,
    const float* __restrict__ W2,  const float* __restrict__ b2)
{
    extern __shared__ char smem[];
    __nv_bfloat16* sWk = (__nv_bfloat16*)(smem);
    __nv_bfloat16* sWv = (__nv_bfloat16*)(smem + 9216);
    __nv_bfloat16* sW1 = (__nv_bfloat16*)(smem + 18432);
    __nv_bfloat16* sW2 = (__nv_bfloat16*)(smem + 35840);
    __nv_bfloat16* sX  = (__nv_bfloat16*)(smem + 54272);
    float*         sTf = (float*)(smem + 63488);          // aliased with sHb
    __nv_bfloat16* sHb = (__nv_bfloat16*)(smem + 63488);
    __nv_bfloat16* sTb = (__nv_bfloat16*)(smem + 80896);
    float*         sV  = (float*)(smem + 90112);
    float*         sG  = (float*)(smem + 92672);

    u32 sb = (u32)__cvta_generic_to_shared(smem);
    const u32 sbWk = sb, sbWv = sb + 9216, sbW1 = sb + 18432, sbW2 = sb + 35840;
    const u32 sbX = sb + 54272, sbHb = sb + 63488, sbTb = sb + 80896;

    const int t = threadIdx.x, warp = t >> 5, lane = t & 31;
    const int mt = warp >> 1, ng = warp & 1;
    const int l15 = lane & 15, lh = lane >> 4, lr = lane >> 2, lc = (lane & 3) * 2;

    for (int i = t; i < 4096; i += 256) {
        int r = i >> 6, c = i & 63;
        sWk[r * 72 + c] = __float2bfloat16(Wk[i]);
        sWv[r * 72 + c] = __float2bfloat16(Wv[i]);
    }
    for (int i = t; i < 8192; i += 256) {
        int r1_ = i >> 7, c1_ = i & 127;
        sW1[r1_ * 136 + c1_] = __float2bfloat16(W1[i]);
        int r2_ = i >> 6, c2_ = i & 63;
        sW2[r2_ * 72 + c2_] = __float2bfloat16(W2[i]);
    }
    if (t < 64) {
        sV[t]       = paW[t];
        sV[64 + t]  = paW[64 + t];
        sV[128 + t] = pab[t];
        sV[192 + t] = lng[t];
        sV[256 + t] = lnb[t];
        sV[320 + t] = peg[t];
        sV[384 + t] = peb[t];
        sV[576 + t] = b2[t];
    }
    if (t < 128) sV[448 + t] = b1[t];
    __syncthreads();

    const float *pa0 = sV, *pa1 = sV + 64, *pbv = sV + 128,
                *sing = sV + 192, *sinb = sV + 256,
                *speg = sV + 320, *speb = sV + 384,
                *sb1 = sV + 448, *sb2v = sV + 576;

    for (int ti = 0; ti < 4; ti++) {
        int tile = blockIdx.x * 4 + ti;          // 8192 tiles of 64 rows
        int rowbase = tile * 64;

        for (int rr = warp; rr < 64; rr += 8) {
            const float* rp = inp + (size_t)(rowbase + rr) * 66;
            float x0 = rp[lane], x1 = rp[lane + 32];
            float s1 = x0 + x1, s2 = x0 * x0 + x1 * x1;
            #pragma unroll
            for (int o = 16; o; o >>= 1) {
                s1 += __shfl_xor_sync(0xffffffffu, s1, o);
                s2 += __shfl_xor_sync(0xffffffffu, s2, o);
            }
            float mu = s1 * 0.015625f;
            float var = s2 * 0.015625f - mu * mu;
            float rs = rsqrtf(var + LNEPS);
            sX[rr * 72 + lane]      = __float2bfloat16((x0 - mu) * rs * sing[lane]      + sinb[lane]);
            sX[rr * 72 + lane + 32] = __float2bfloat16((x1 - mu) * rs * sing[lane + 32] + sinb[lane + 32]);
            if (lane < 2) sG[rr * 2 + lane] = rp[64 + lane];
        }
        __syncthreads();

        #pragma unroll 1
        for (int pass = 0; pass < 2; pass++) {
            const u32 sbW = pass ? sbWv : sbWk;
            unsigned* outg = pass ? g_vh : g_kh;

            {
                float acc[4][4];
                #pragma unroll
                for (int s = 0; s < 4; s++)
                    #pragma unroll
                    for (int j = 0; j < 4; j++) acc[s][j] = 0.f;

                #pragma unroll
                for (int ks = 0; ks < 4; ks++) {
                    u32 a[4];
                    ldsm_x4(a, sbX + ((mt * 16 + l15) * 72 + ks * 16 + lh * 8) * 2);
                    #pragma unroll
                    for (int s = 0; s < 4; s++) {
                        u32 b[2];
                        int nb = ng * 32 + s * 8;
                        ldsm_x2t(b, sbW + ((ks * 16 + l15) * 72 + nb) * 2);
                        mma_bf16(acc[s], a, b);
                    }
                }
                int r0 = mt * 16 + lr, r1 = r0 + 8;
                float gx0 = sG[r0 * 2], gy0 = sG[r0 * 2 + 1];
                float gx1 = sG[r1 * 2], gy1 = sG[r1 * 2 + 1];
                #pragma unroll
                for (int s = 0; s < 4; s++) {
                    int c = ng * 32 + s * 8 + lc;
                    float p0a = pa0[c], p0b = pa0[c + 1];
                    float p1a = pa1[c], p1b = pa1[c + 1];
                    float pba = pbv[c], pbb = pbv[c + 1];
                    *(float2*)&sTf[r0 * 66 + c] =
                        make_float2(acc[s][0] + gx0 * p0a + gy0 * p1a + pba,
                                    acc[s][1] + gx0 * p0b + gy0 * p1b + pbb);
                    *(float2*)&sTf[r1 * 66 + c] =
                        make_float2(acc[s][2] + gx1 * p0a + gy1 * p1a + pba,
                                    acc[s][3] + gx1 * p0b + gy1 * p1b + pbb);
                }
            }
            __syncthreads();

            for (int rr = warp; rr < 64; rr += 8) {
                float x0 = sTf[rr * 66 + lane], x1 = sTf[rr * 66 + lane + 32];
                float s1 = x0 + x1, s2 = x0 * x0 + x1 * x1;
                #pragma unroll
                for (int o = 16; o; o >>= 1) {
                    s1 += __shfl_xor_sync(0xffffffffu, s1, o);
                    s2 += __shfl_xor_sync(0xffffffffu, s2, o);
                }
                float mu = s1 * 0.015625f;
                float var = s2 * 0.015625f - mu * mu;
                float rs = rsqrtf(var + LNEPS);
                sTb[rr * 72 + lane]      = __float2bfloat16((x0 - mu) * rs * speg[lane]      + speb[lane]);
                sTb[rr * 72 + lane + 32] = __float2bfloat16((x1 - mu) * rs * speg[lane + 32] + speb[lane + 32]);
            }
            __syncthreads();

            {
                float acc[8][4];
                #pragma unroll
                for (int s = 0; s < 8; s++)
                    #pragma unroll
                    for (int j = 0; j < 4; j++) acc[s][j] = 0.f;

                #pragma unroll
                for (int ks = 0; ks < 4; ks++) {
                    u32 a[4];
                    ldsm_x4(a, sbTb + ((mt * 16 + l15) * 72 + ks * 16 + lh * 8) * 2);
                    #pragma unroll
                    for (int s = 0; s < 8; s++) {
                        u32 b[2];
                        int nb = ng * 64 + s * 8;
                        ldsm_x2t(b, sbW1 + ((ks * 16 + l15) * 136 + nb) * 2);
                        mma_bf16(acc[s], a, b);
                    }
                }
                __syncthreads();   // Tf reads done before H overwrite (alias safety)
                int r0 = mt * 16 + lr, r1 = r0 + 8;
                #pragma unroll
                for (int s = 0; s < 8; s++) {
                    int c = ng * 64 + s * 8 + lc;
                    float ba = sb1[c], bb = sb1[c + 1];
                    *(u32*)&sHb[r0 * 136 + c] =
                        bf2u(fmaxf(acc[s][0] + ba, 0.f), fmaxf(acc[s][1] + bb, 0.f));
                    *(u32*)&sHb[r1 * 136 + c] =
                        bf2u(fmaxf(acc[s][2] + ba, 0.f), fmaxf(acc[s][3] + bb, 0.f));
                }
            }
            __syncthreads();

            {
                float acc[4][4];
                #pragma unroll
                for (int s = 0; s < 4; s++)
                    #pragma unroll
                    for (int j = 0; j < 4; j++) acc[s][j] = 0.f;

                #pragma unroll
                for (int ks = 0; ks < 8; ks++) {
                    u32 a[4];
                    ldsm_x4(a, sbHb + ((mt * 16 + l15) * 136 + ks * 16 + lh * 8) * 2);
                    #pragma unroll
                    for (int s = 0; s < 4; s++) {
                        u32 b[2];
                        int nb = ng * 32 + s * 8;
                        ldsm_x2t(b, sbW2 + ((ks * 16 + l15) * 72 + nb) * 2);
                        mma_bf16(acc[s], a, b);
                    }
                }
                int r0 = mt * 16 + lr, r1 = r0 + 8;
                #pragma unroll
                for (int s = 0; s < 4; s++) {
                    int c = ng * 32 + s * 8 + lc;
                    float ba = sb2v[c], bb = sb2v[c + 1];
                    outg[(size_t)(rowbase + r0) * 32 + (c >> 1)] =
                        bf2u(acc[s][0] + ba, acc[s][1] + bb);
                    outg[(size_t)(rowbase + r1) * 32 + (c >> 1)] =
                        bf2u(acc[s][2] + ba, acc[s][3] + bb);
                }
            }
            __syncthreads();
        }
    }
}

// ---------------------------------------------------------------------------
// initq: s = broadcast(slots); q = LN(s; ln_s) @ Wq  (one block per b)
// ---------------------------------------------------------------------------
__global__ __launch_bounds__(256) void initq_kernel(
    const float* __restrict__ slots,
    const float* __restrict__ lnsg, const float* __restrict__ lnsb,
    const float* __restrict__ Wq)
{
    __shared__ float ss[512], sln[512];
    int b = blockIdx.x, t = threadIdx.x, warp = t >> 5, lane = t & 31;
    for (int i = t; i < 512; i += 256) {
        float v = slots[i];
        g_s[b * 512 + i] = v;
        ss[i] = v;
    }
    __syncthreads();
    {
        const float* row = ss + warp * 64;
        float x0 = row[lane], x1 = row[lane + 32];
        float s1 = x0 + x1, s2 = x0 * x0 + x1 * x1;
        #pragma unroll
        for (int o = 16; o; o >>= 1) {
            s1 += __shfl_xor_sync(0xffffffffu, s1, o);
            s2 += __shfl_xor_sync(0xffffffffu, s2, o);
        }
        float mu = s1 * 0.015625f;
        float var = s2 * 0.015625f - mu * mu;
        float rs = rsqrtf(var + LNEPS);
        sln[warp * 64 + lane]      = (x0 - mu) * rs * lnsg[lane]      + lnsb[lane];
        sln[warp * 64 + lane + 32] = (x1 - mu) * rs * lnsg[lane + 32] + lnsb[lane + 32];
    }
    __syncthreads();
    for (int i = t; i < 512; i += 256) {
        int s = i >> 6, c = i & 63;
        float a = 0.f;
        #pragma unroll 8
        for (int d = 0; d < 64; d++) a += sln[s * 64 + d] * Wq[d * 64 + c];
        g_q[b * 512 + i] = a;
    }
}

// ---------------------------------------------------------------------------
// Attention (unchanged from R11): HMMA logits + quad-shuffle softmax.
// ---------------------------------------------------------------------------
#define ATTN_SMEM_BYTES 62720

__global__ __launch_bounds__(256) void attn_kernel()
{
    extern __shared__ char smc[];
    __nv_bfloat16* qTb = (__nv_bfloat16*)smc;     // [64][8]
    u32*   sKu  = (u32*)(smc + 1024);             // per-warp [32][36]
    float* sAb  = (float*)(smc + 37888);          // per-warp [32][8]
    float* wacc = (float*)(smc + 46080);          // [8][520]

    u32 sb = (u32)__cvta_generic_to_shared(smc);
    const u32 sbQ = sb, sbK = sb + 1024;

    int b = blockIdx.x >> 6, pb = blockIdx.x & 63;
    int t = threadIdx.x, warp = t >> 5, lane = t & 31;
    const int l15 = lane & 15, lh = lane >> 4;
    const int q = lane >> 2, c0 = (lane & 3) * 2;

    for (int i = t; i < 512; i += 256) {
        int s = i >> 6, d = i & 63;
        qTb[d * 8 + s] = __float2bfloat16(g_q[b * 512 + i]);
    }
    __syncthreads();

    u32 qf[4][2];
    #pragma unroll
    for (int kc = 0; kc < 4; kc++)
        ldsm_x2t(qf[kc], sbQ + ((kc * 16 + l15) * 8) * 2);

    size_t rowbase = (size_t)b * N_ + pb * 256 + warp * 32;
    const unsigned* kp = g_kh + rowbase * 32;
    const unsigned* vp = g_vh + rowbase * 32;

    u32* mk = sKu + warp * 1152;
    const u32 wbase = sbK + warp * 4608;
    #pragma unroll 4
    for (int i = 0; i < 32; i++) mk[i * 36 + lane] = kp[i * 32 + lane];
    __syncwarp();

    float acc[2][4];
    #pragma unroll
    for (int m = 0; m < 2; m++)
        #pragma unroll
        for (int j = 0; j < 4; j++) acc[m][j] = 0.f;
    #pragma unroll
    for (int m = 0; m < 2; m++) {
        #pragma unroll
        for (int kc = 0; kc < 4; kc++) {
            u32 a[4];
            ldsm_x4(a, wbase + ((m * 16 + l15) * 72 + kc * 16 + lh * 8) * 2);
            mma_bf16(acc[m], a, qf[kc]);
        }
    }

    float den0 = 0.f, den1 = 0.f;
    float* paw = sAb + warp * 256;
    #pragma unroll
    for (int m = 0; m < 2; m++) {
        #pragma unroll
        for (int h = 0; h < 2; h++) {
            float e0 = acc[m][h * 2]     * 0.125f;
            float e1 = acc[m][h * 2 + 1] * 0.125f;
            float mx = fmaxf(e0, e1);
            mx = fmaxf(mx, __shfl_xor_sync(0xffffffffu, mx, 1));
            mx = fmaxf(mx, __shfl_xor_sync(0xffffffffu, mx, 2));
            e0 = __expf(e0 - mx); e1 = __expf(e1 - mx);
            float se = e0 + e1;
            se += __shfl_xor_sync(0xffffffffu, se, 1);
            se += __shfl_xor_sync(0xffffffffu, se, 2);
            float inv = 1.f / se;
            e0 = e0 * inv + ATTN_EPS;
            e1 = e1 * inv + ATTN_EPS;
            int row = m * 16 + h * 8 + q;
            paw[row * 8 + c0]     = e0;
            paw[row * 8 + c0 + 1] = e1;
            den0 += e0; den1 += e1;
        }
    }
    den0 += __shfl_xor_sync(0xffffffffu, den0, 4);
    den0 += __shfl_xor_sync(0xffffffffu, den0, 8);
    den0 += __shfl_xor_sync(0xffffffffu, den0, 16);
    den1 += __shfl_xor_sync(0xffffffffu, den1, 4);
    den1 += __shfl_xor_sync(0xffffffffu, den1, 8);
    den1 += __shfl_xor_sync(0xffffffffu, den1, 16);
    __syncwarp();

    #pragma unroll 4
    for (int i = 0; i < 32; i++) mk[i * 36 + lane] = vp[i * 32 + lane];
    __syncwarp();

    float acc0[8], acc1[8];
    #pragma unroll
    for (int s = 0; s < 8; s++) { acc0[s] = 0.f; acc1[s] = 0.f; }
    #pragma unroll 4
    for (int i = 0; i < 32; i++) {
        float2 v = u2f2(mk[i * 36 + lane]);
        float4 a0 = *(const float4*)(paw + i * 8);
        float4 a1 = *(const float4*)(paw + i * 8 + 4);
        acc0[0] += a0.x * v.x; acc1[0] += a0.x * v.y;
        acc0[1] += a0.y * v.x; acc1[1] += a0.y * v.y;
        acc0[2] += a0.z * v.x; acc1[2] += a0.z * v.y;
        acc0[3] += a0.w * v.x; acc1[3] += a0.w * v.y;
        acc0[4] += a1.x * v.x; acc1[4] += a1.x * v.y;
        acc0[5] += a1.y * v.x; acc1[5] += a1.y * v.y;
        acc0[6] += a1.z * v.x; acc1[6] += a1.z * v.y;
        acc0[7] += a1.w * v.x; acc1[7] += a1.w * v.y;
    }

    float* wa = wacc + warp * 520;
    #pragma unroll
    for (int s = 0; s < 8; s++) {
        wa[s * 64 + lane * 2]     = acc0[s];
        wa[s * 64 + lane * 2 + 1] = acc1[s];
    }
    if (lane < 4) {
        wa[512 + c0]     = den0;
        wa[512 + c0 + 1] = den1;
    }
    __syncthreads();

    float* dst = g_part + (size_t)blockIdx.x * 520;
    for (int i = t; i < 520; i += 256) {
        float v = 0.f;
        #pragma unroll
        for (int w = 0; w < 8; w++) v += wacc[w * 520 + i];
        dst[i] = v;
    }
}

// ---------------------------------------------------------------------------
// update: one block per (b, slot). Reduce own partials -> GRU -> MLP ->
// residual -> next q. 256 blocks of 256 threads.
// ---------------------------------------------------------------------------
__global__ __launch_bounds__(256) void update_kernel(
    const float* __restrict__ W_ih, const float* __restrict__ W_hh,
    const float* __restrict__ b_ih, const float* __restrict__ b_hh,
    const float* __restrict__ lnmg, const float* __restrict__ lnmb,
    const float* __restrict__ mW1,  const float* __restrict__ mb1,
    const float* __restrict__ mW2,  const float* __restrict__ mb2,
    const float* __restrict__ lnsg, const float* __restrict__ lnsb,
    const float* __restrict__ Wq,
    float* __restrict__ dout)
{
    __shared__ float u[64], prev[64], gx[192], gh[192];
    __shared__ float snew[64], sln[64], h1[128], red[65];
    int b = blockIdx.x >> 3, s = blockIdx.x & 7;
    int t = threadIdx.x, warp = t >> 5, lane = t & 31;

    // ---- reduce this slot's partials over 64 attn blocks ----
    if (t < 65) {
        int idx = (t < 64) ? (s * 64 + t) : (512 + s);
        const float* p = g_part + (size_t)(b * 64) * 520 + idx;
        float v = 0.f;
        #pragma unroll 8
        for (int pp = 0; pp < 64; pp++) v += p[pp * 520];
        red[t] = v;
    }
    if (t >= 192 && t < 256) prev[t - 192] = g_s[b * 512 + s * 64 + (t - 192)];
    __syncthreads();

    if (t < 64) u[t] = red[t] / red[64];
    __syncthreads();

    // ---- gx = u @ W_ih + b_ih ; gh = prev @ W_hh + b_hh (t<192 each) ----
    if (t < 192) {
        float ax = b_ih[t], ah = b_hh[t];
        #pragma unroll 8
        for (int d = 0; d < 64; d++) {
            ax += u[d]    * W_ih[d * 192 + t];
            ah += prev[d] * W_hh[d * 192 + t];
        }
        gx[t] = ax; gh[t] = ah;
    }
    __syncthreads();

    // ---- GRU gates ----
    if (t < 64) {
        float xr = gx[t], xz = gx[64 + t], xn = gx[128 + t];
        float hr = gh[t], hz = gh[64 + t], hn = gh[128 + t];
        float r_ = 1.f / (1.f + __expf(-(xr + hr)));
        float z  = 1.f / (1.f + __expf(-(xz + hz)));
        float nn = tanhf(xn + r_ * hn);
        snew[t] = (1.f - z) * nn + z * prev[t];
    }
    __syncthreads();

    // ---- LN(snew; ln_m) (warp 0) ----
    if (warp == 0) {
        float x0 = snew[lane], x1 = snew[lane + 32];
        float s1 = x0 + x1, s2 = x0 * x0 + x1 * x1;
        #pragma unroll
        for (int o = 16; o; o >>= 1) {
            s1 += __shfl_xor_sync(0xffffffffu, s1, o);
            s2 += __shfl_xor_sync(0xffffffffu, s2, o);
        }
        float mu = s1 * 0.015625f;
        float var = s2 * 0.015625f - mu * mu;
        float rs = rsqrtf(var + LNEPS);
        sln[lane]      = (x0 - mu) * rs * lnmg[lane]      + lnmb[lane];
        sln[lane + 32] = (x1 - mu) * rs * lnmg[lane + 32] + lnmb[lane + 32];
    }
    __syncthreads();

    // ---- h1 = relu(sln @ mlp_W1 + b1) ----
    if (t < 128) {
        float a = mb1[t];
        #pragma unroll 8
        for (int d = 0; d < 64; d++) a += sln[d] * mW1[d * 128 + t];
        h1[t] = fmaxf(a, 0.f);
    }
    __syncthreads();

    // ---- s = snew + h1 @ mlp_W2 + b2 ----
    if (t < 64) {
        float a = mb2[t];
        #pragma unroll 8
        for (int k = 0; k < 128; k++) a += h1[k] * mW2[k * 64 + t];
        float val = snew[t] + a;
        g_s[b * 512 + s * 64 + t] = val;
        dout[b * 512 + s * 64 + t] = val;
        u[t] = val;   // reuse for next-q LN
    }
    __syncthreads();

    // ---- fused next q: LN(s_new; ln_s) @ Wq ----
    if (warp == 0) {
        float x0 = u[lane], x1 = u[lane + 32];
        float s1 = x0 + x1, s2 = x0 * x0 + x1 * x1;
        #pragma unroll
        for (int o = 16; o; o >>= 1) {
            s1 += __shfl_xor_sync(0xffffffffu, s1, o);
            s2 += __shfl_xor_sync(0xffffffffu, s2, o);
        }
        float mu = s1 * 0.015625f;
        float var = s2 * 0.015625f - mu * mu;
        float rs = rsqrtf(var + LNEPS);
        sln[lane]      = (x0 - mu) * rs * lnsg[lane]      + lnsb[lane];
        sln[lane + 32] = (x1 - mu) * rs * lnsg[lane + 32] + lnsb[lane + 32];
    }
    __syncthreads();
    if (t < 64) {
        float a = 0.f;
        #pragma unroll 8
        for (int d = 0; d < 64; d++) a += sln[d] * Wq[d * 64 + t];
        g_q[b * 512 + s * 64 + t] = a;
    }
}

// ---------------------------------------------------------------------------
extern "C" void kernel_launch(void* const* d_in, const int* in_sizes, int n_in,
                              void* d_out, int out_size)
{
    (void)in_sizes; (void)n_in; (void)out_size;
    const float* inputs  = (const float*)d_in[0];
    const float* slots   = (const float*)d_in[1];
    const float* ln_in_g = (const float*)d_in[2];
    const float* ln_in_b = (const float*)d_in[3];
    const float* ln_s_g  = (const float*)d_in[4];
    const float* ln_s_b  = (const float*)d_in[5];
    const float* ln_m_g  = (const float*)d_in[6];
    const float* ln_m_b  = (const float*)d_in[7];
    const float* Wq      = (const float*)d_in[8];
    const float* Wk      = (const float*)d_in[9];
    const float* Wv      = (const float*)d_in[10];
    const float* W_ih    = (const float*)d_in[11];
    const float* W_hh    = (const float*)d_in[12];
    const float* b_ih    = (const float*)d_in[13];
    const float* b_hh    = (const float*)d_in[14];
    const float* mlp_W1  = (const float*)d_in[15];
    const float* mlp_b1  = (const float*)d_in[16];
    const float* mlp_W2  = (const float*)d_in[17];
    const float* mlp_b2  = (const float*)d_in[18];
    const float* pa_W    = (const float*)d_in[19];
    const float* pa_b    = (const float*)d_in[20];
    const float* pe_g    = (const float*)d_in[21];
    const float* pe_b    = (const float*)d_in[22];
    const float* pe_W1   = (const float*)d_in[23];
    const float* pe_b1   = (const float*)d_in[24];
    const float* pe_W2   = (const float*)d_in[25];
    const float* pe_b2   = (const float*)d_in[26];
    float* out = (float*)d_out;

    static int configured = 0;
    if (!configured) {
        cudaFuncSetAttribute(preprocess_kernel,
                             cudaFuncAttributeMaxDynamicSharedMemorySize, PRE_SMEM_BYTES);
        cudaFuncSetAttribute(attn_kernel,
                             cudaFuncAttributeMaxDynamicSharedMemorySize, ATTN_SMEM_BYTES);
        configured = 1;
    }

    preprocess_kernel<<<2048, 256, PRE_SMEM_BYTES>>>(
        inputs, ln_in_g, ln_in_b, Wk, Wv, pa_W, pa_b, pe_g, pe_b,
        pe_W1, pe_b1, pe_W2, pe_b2);

    initq_kernel<<<32, 256>>>(slots, ln_s_g, ln_s_b, Wq);

    for (int it = 0; it < 3; it++) {
        attn_kernel<<<2048, 256, ATTN_SMEM_BYTES>>>();
        update_kernel<<<256, 256>>>(W_ih, W_hh, b_ih, b_hh,
                                    ln_m_g, ln_m_b,
                                    mlp_W1, mlp_b1, mlp_W2, mlp_b2,
                                    ln_s_g, ln_s_b, Wq, out);
    }
}

// round 13
// speedup vs baseline: 1.5505x; 1.0935x over previous
#include <cuda_runtime.h>
#include <cuda_bf16.h>
#include <cmath>

#define B_ 32
#define N_ 16384
#define D_ 64
#define S_ 8
#define H_ 128
#define LNEPS 1e-5f
#define ATTN_EPS 1e-8f

typedef unsigned long long ull;
typedef unsigned int u32;

// ---------------- scratch (device globals; no allocations allowed) ----------
__device__ unsigned g_kh[B_ * N_ * 32];   // k_pos bf16x2 (64 MB)
__device__ unsigned g_vh[B_ * N_ * 32];   // v_pos bf16x2 (64 MB)
__device__ float g_q[B_ * S_ * D_];
__device__ float g_s[B_ * S_ * D_];
__device__ float g_part[B_ * 64 * 520];   // per-(b, partial-block) numer(512)+den(8)

// ---------------- helpers ----------------------------------------------------
__device__ __forceinline__ unsigned bf2u(float a, float b) {
    __nv_bfloat162 h = __float22bfloat162_rn(make_float2(a, b));
    return *(unsigned*)&h;
}
__device__ __forceinline__ float2 u2f2(unsigned u) {
    __nv_bfloat162 h = *(__nv_bfloat162*)&u;
    return __bfloat1622float2(h);
}
__device__ __forceinline__ void ldsm_x4(u32 a[4], u32 addr) {
    asm volatile("ldmatrix.sync.aligned.m8n8.x4.shared.b16 {%0,%1,%2,%3}, [%4];"
                 : "=r"(a[0]), "=r"(a[1]), "=r"(a[2]), "=r"(a[3]) : "r"(addr));
}
__device__ __forceinline__ void ldsm_x2t(u32 b[2], u32 addr) {
    asm volatile("ldmatrix.sync.aligned.m8n8.x2.trans.shared.b16 {%0,%1}, [%2];"
                 : "=r"(b[0]), "=r"(b[1]) : "r"(addr));
}
__device__ __forceinline__ void mma_bf16(float d[4], const u32 a[4], const u32 b[2]) {
    asm volatile("mma.sync.aligned.m16n8k16.row.col.f32.bf16.bf16.f32 "
                 "{%0,%1,%2,%3},{%4,%5,%6,%7},{%8,%9},{%0,%1,%2,%3};"
                 : "+f"(d[0]), "+f"(d[1]), "+f"(d[2]), "+f"(d[3])
                 : "r"(a[0]), "r"(a[1]), "r"(a[2]), "r"(a[3]), "r"(b[0]), "r"(b[1]));
}

// ---------------------------------------------------------------------------
// Kernel 1: fused preprocessing (unchanged from R11/R12 best).
// ---------------------------------------------------------------------------
#define PRE_SMEM_BYTES 93184

__global__ __launch_bounds__(256, 2) void preprocess_kernel(
    const float* __restrict__ inp,
    const float* __restrict__ lng, const float* __restrict__ lnb,
    const float* __restrict__ Wk,  const float* __restrict__ Wv,
    const float* __restrict__ paW, const float* __restrict__ pab,
    const float* __restrict__ peg, const float* __restrict__ peb,
    const float* __restrict__ W1,  const float* __restrict__ b1,
    const float* __restrict__ W2,  const float* __restrict__ b2)
{
    extern __shared__ char smem[];
    __nv_bfloat16* sWk = (__nv_bfloat16*)(smem);
    __nv_bfloat16* sWv = (__nv_bfloat16*)(smem + 9216);
    __nv_bfloat16* sW1 = (__nv_bfloat16*)(smem + 18432);
    __nv_bfloat16* sW2 = (__nv_bfloat16*)(smem + 35840);
    __nv_bfloat16* sX  = (__nv_bfloat16*)(smem + 54272);
    float*         sTf = (float*)(smem + 63488);          // aliased with sHb
    __nv_bfloat16* sHb = (__nv_bfloat16*)(smem + 63488);
    __nv_bfloat16* sTb = (__nv_bfloat16*)(smem + 80896);
    float*         sV  = (float*)(smem + 90112);
    float*         sG  = (float*)(smem + 92672);

    u32 sb = (u32)__cvta_generic_to_shared(smem);
    const u32 sbWk = sb, sbWv = sb + 9216, sbW1 = sb + 18432, sbW2 = sb + 35840;
    const u32 sbX = sb + 54272, sbHb = sb + 63488, sbTb = sb + 80896;

    const int t = threadIdx.x, warp = t >> 5, lane = t & 31;
    const int mt = warp >> 1, ng = warp & 1;
    const int l15 = lane & 15, lh = lane >> 4, lr = lane >> 2, lc = (lane & 3) * 2;

    for (int i = t; i < 4096; i += 256) {
        int r = i >> 6, c = i & 63;
        sWk[r * 72 + c] = __float2bfloat16(Wk[i]);
        sWv[r * 72 + c] = __float2bfloat16(Wv[i]);
    }
    for (int i = t; i < 8192; i += 256) {
        int r1_ = i >> 7, c1_ = i & 127;
        sW1[r1_ * 136 + c1_] = __float2bfloat16(W1[i]);
        int r2_ = i >> 6, c2_ = i & 63;
        sW2[r2_ * 72 + c2_] = __float2bfloat16(W2[i]);
    }
    if (t < 64) {
        sV[t]       = paW[t];
        sV[64 + t]  = paW[64 + t];
        sV[128 + t] = pab[t];
        sV[192 + t] = lng[t];
        sV[256 + t] = lnb[t];
        sV[320 + t] = peg[t];
        sV[384 + t] = peb[t];
        sV[576 + t] = b2[t];
    }
    if (t < 128) sV[448 + t] = b1[t];
    __syncthreads();

    const float *pa0 = sV, *pa1 = sV + 64, *pbv = sV + 128,
                *sing = sV + 192, *sinb = sV + 256,
                *speg = sV + 320, *speb = sV + 384,
                *sb1 = sV + 448, *sb2v = sV + 576;

    for (int ti = 0; ti < 4; ti++) {
        int tile = blockIdx.x * 4 + ti;          // 8192 tiles of 64 rows
        int rowbase = tile * 64;

        for (int rr = warp; rr < 64; rr += 8) {
            const float* rp = inp + (size_t)(rowbase + rr) * 66;
            float x0 = rp[lane], x1 = rp[lane + 32];
            float s1 = x0 + x1, s2 = x0 * x0 + x1 * x1;
            #pragma unroll
            for (int o = 16; o; o >>= 1) {
                s1 += __shfl_xor_sync(0xffffffffu, s1, o);
                s2 += __shfl_xor_sync(0xffffffffu, s2, o);
            }
            float mu = s1 * 0.015625f;
            float var = s2 * 0.015625f - mu * mu;
            float rs = rsqrtf(var + LNEPS);
            sX[rr * 72 + lane]      = __float2bfloat16((x0 - mu) * rs * sing[lane]      + sinb[lane]);
            sX[rr * 72 + lane + 32] = __float2bfloat16((x1 - mu) * rs * sing[lane + 32] + sinb[lane + 32]);
            if (lane < 2) sG[rr * 2 + lane] = rp[64 + lane];
        }
        __syncthreads();

        #pragma unroll 1
        for (int pass = 0; pass < 2; pass++) {
            const u32 sbW = pass ? sbWv : sbWk;
            unsigned* outg = pass ? g_vh : g_kh;

            {
                float acc[4][4];
                #pragma unroll
                for (int s = 0; s < 4; s++)
                    #pragma unroll
                    for (int j = 0; j < 4; j++) acc[s][j] = 0.f;

                #pragma unroll
                for (int ks = 0; ks < 4; ks++) {
                    u32 a[4];
                    ldsm_x4(a, sbX + ((mt * 16 + l15) * 72 + ks * 16 + lh * 8) * 2);
                    #pragma unroll
                    for (int s = 0; s < 4; s++) {
                        u32 b[2];
                        int nb = ng * 32 + s * 8;
                        ldsm_x2t(b, sbW + ((ks * 16 + l15) * 72 + nb) * 2);
                        mma_bf16(acc[s], a, b);
                    }
                }
                int r0 = mt * 16 + lr, r1 = r0 + 8;
                float gx0 = sG[r0 * 2], gy0 = sG[r0 * 2 + 1];
                float gx1 = sG[r1 * 2], gy1 = sG[r1 * 2 + 1];
                #pragma unroll
                for (int s = 0; s < 4; s++) {
                    int c = ng * 32 + s * 8 + lc;
                    float p0a = pa0[c], p0b = pa0[c + 1];
                    float p1a = pa1[c], p1b = pa1[c + 1];
                    float pba = pbv[c], pbb = pbv[c + 1];
                    *(float2*)&sTf[r0 * 66 + c] =
                        make_float2(acc[s][0] + gx0 * p0a + gy0 * p1a + pba,
                                    acc[s][1] + gx0 * p0b + gy0 * p1b + pbb);
                    *(float2*)&sTf[r1 * 66 + c] =
                        make_float2(acc[s][2] + gx1 * p0a + gy1 * p1a + pba,
                                    acc[s][3] + gx1 * p0b + gy1 * p1b + pbb);
                }
            }
            __syncthreads();

            for (int rr = warp; rr < 64; rr += 8) {
                float x0 = sTf[rr * 66 + lane], x1 = sTf[rr * 66 + lane + 32];
                float s1 = x0 + x1, s2 = x0 * x0 + x1 * x1;
                #pragma unroll
                for (int o = 16; o; o >>= 1) {
                    s1 += __shfl_xor_sync(0xffffffffu, s1, o);
                    s2 += __shfl_xor_sync(0xffffffffu, s2, o);
                }
                float mu = s1 * 0.015625f;
                float var = s2 * 0.015625f - mu * mu;
                float rs = rsqrtf(var + LNEPS);
                sTb[rr * 72 + lane]      = __float2bfloat16((x0 - mu) * rs * speg[lane]      + speb[lane]);
                sTb[rr * 72 + lane + 32] = __float2bfloat16((x1 - mu) * rs * speg[lane + 32] + speb[lane + 32]);
            }
            __syncthreads();

            {
                float acc[8][4];
                #pragma unroll
                for (int s = 0; s < 8; s++)
                    #pragma unroll
                    for (int j = 0; j < 4; j++) acc[s][j] = 0.f;

                #pragma unroll
                for (int ks = 0; ks < 4; ks++) {
                    u32 a[4];
                    ldsm_x4(a, sbTb + ((mt * 16 + l15) * 72 + ks * 16 + lh * 8) * 2);
                    #pragma unroll
                    for (int s = 0; s < 8; s++) {
                        u32 b[2];
                        int nb = ng * 64 + s * 8;
                        ldsm_x2t(b, sbW1 + ((ks * 16 + l15) * 136 + nb) * 2);
                        mma_bf16(acc[s], a, b);
                    }
                }
                __syncthreads();   // Tf reads done before H overwrite (alias safety)
                int r0 = mt * 16 + lr, r1 = r0 + 8;
                #pragma unroll
                for (int s = 0; s < 8; s++) {
                    int c = ng * 64 + s * 8 + lc;
                    float ba = sb1[c], bb = sb1[c + 1];
                    *(u32*)&sHb[r0 * 136 + c] =
                        bf2u(fmaxf(acc[s][0] + ba, 0.f), fmaxf(acc[s][1] + bb, 0.f));
                    *(u32*)&sHb[r1 * 136 + c] =
                        bf2u(fmaxf(acc[s][2] + ba, 0.f), fmaxf(acc[s][3] + bb, 0.f));
                }
            }
            __syncthreads();

            {
                float acc[4][4];
                #pragma unroll
                for (int s = 0; s < 4; s++)
                    #pragma unroll
                    for (int j = 0; j < 4; j++) acc[s][j] = 0.f;

                #pragma unroll
                for (int ks = 0; ks < 8; ks++) {
                    u32 a[4];
                    ldsm_x4(a, sbHb + ((mt * 16 + l15) * 136 + ks * 16 + lh * 8) * 2);
                    #pragma unroll
                    for (int s = 0; s < 4; s++) {
                        u32 b[2];
                        int nb = ng * 32 + s * 8;
                        ldsm_x2t(b, sbW2 + ((ks * 16 + l15) * 72 + nb) * 2);
                        mma_bf16(acc[s], a, b);
                    }
                }
                int r0 = mt * 16 + lr, r1 = r0 + 8;
                #pragma unroll
                for (int s = 0; s < 4; s++) {
                    int c = ng * 32 + s * 8 + lc;
                    float ba = sb2v[c], bb = sb2v[c + 1];
                    outg[(size_t)(rowbase + r0) * 32 + (c >> 1)] =
                        bf2u(acc[s][0] + ba, acc[s][1] + bb);
                    outg[(size_t)(rowbase + r1) * 32 + (c >> 1)] =
                        bf2u(acc[s][2] + ba, acc[s][3] + bb);
                }
            }
            __syncthreads();
        }
    }
}

// ---------------------------------------------------------------------------
// initq: s = broadcast(slots); q = LN(s; ln_s) @ Wq  (one block per b)
// ---------------------------------------------------------------------------
__global__ __launch_bounds__(256) void initq_kernel(
    const float* __restrict__ slots,
    const float* __restrict__ lnsg, const float* __restrict__ lnsb,
    const float* __restrict__ Wq)
{
    __shared__ float ss[512], sln[512];
    int b = blockIdx.x, t = threadIdx.x, warp = t >> 5, lane = t & 31;
    for (int i = t; i < 512; i += 256) {
        float v = slots[i];
        g_s[b * 512 + i] = v;
        ss[i] = v;
    }
    __syncthreads();
    {
        const float* row = ss + warp * 64;
        float x0 = row[lane], x1 = row[lane + 32];
        float s1 = x0 + x1, s2 = x0 * x0 + x1 * x1;
        #pragma unroll
        for (int o = 16; o; o >>= 1) {
            s1 += __shfl_xor_sync(0xffffffffu, s1, o);
            s2 += __shfl_xor_sync(0xffffffffu, s2, o);
        }
        float mu = s1 * 0.015625f;
        float var = s2 * 0.015625f - mu * mu;
        float rs = rsqrtf(var + LNEPS);
        sln[warp * 64 + lane]      = (x0 - mu) * rs * lnsg[lane]      + lnsb[lane];
        sln[warp * 64 + lane + 32] = (x1 - mu) * rs * lnsg[lane + 32] + lnsb[lane + 32];
    }
    __syncthreads();
    for (int i = t; i < 512; i += 256) {
        int s = i >> 6, c = i & 63;
        float a = 0.f;
        #pragma unroll 8
        for (int d = 0; d < 64; d++) a += sln[s * 64 + d] * Wq[d * 64 + c];
        g_q[b * 512 + i] = a;
    }
}

// ---------------------------------------------------------------------------
// Attention: HMMA logits + quad-shuffle softmax; v tile preloaded to
// REGISTERS at entry (latency hidden behind logits/softmax).
// smem: qTb bf16[64][8] @0 (1024) | sKu u32 per-warp [32][36] @1024 (36864) |
//       sAb f32 per-warp [32][8] @37888 (8192) | wacc [8][520] @46080 (16640)
//       -> 62720 B (3 CTAs/SM)
// ---------------------------------------------------------------------------
#define ATTN_SMEM_BYTES 62720

__global__ __launch_bounds__(256, 3) void attn_kernel()
{
    extern __shared__ char smc[];
    __nv_bfloat16* qTb = (__nv_bfloat16*)smc;     // [64][8]
    u32*   sKu  = (u32*)(smc + 1024);             // per-warp [32][36]
    float* sAb  = (float*)(smc + 37888);          // per-warp [32][8]
    float* wacc = (float*)(smc + 46080);          // [8][520]

    u32 sb = (u32)__cvta_generic_to_shared(smc);
    const u32 sbQ = sb, sbK = sb + 1024;

    int b = blockIdx.x >> 6, pb = blockIdx.x & 63;
    int t = threadIdx.x, warp = t >> 5, lane = t & 31;
    const int l15 = lane & 15, lh = lane >> 4;
    const int q = lane >> 2, c0 = (lane & 3) * 2;

    for (int i = t; i < 512; i += 256) {
        int s = i >> 6, d = i & 63;
        qTb[d * 8 + s] = __float2bfloat16(g_q[b * 512 + i]);
    }
    __syncthreads();

    u32 qf[4][2];
    #pragma unroll
    for (int kc = 0; kc < 4; kc++)
        ldsm_x2t(qf[kc], sbQ + ((kc * 16 + l15) * 8) * 2);

    size_t rowbase = (size_t)b * N_ + pb * 256 + warp * 32;
    const unsigned* kp = g_kh + rowbase * 32;
    const unsigned* vp = g_vh + rowbase * 32;

    // stage k tile; also kick off ALL v loads into registers (latency hides
    // behind the HMMA logits + softmax below)
    u32* mk = sKu + warp * 1152;
    const u32 wbase = sbK + warp * 4608;
    #pragma unroll
    for (int i = 0; i < 32; i++) mk[i * 36 + lane] = kp[i * 32 + lane];
    u32 vreg[32];
    #pragma unroll
    for (int i = 0; i < 32; i++) vreg[i] = vp[i * 32 + lane];
    __syncwarp();

    // logits via HMMA: L[32x8] = K[32x64] @ Q^T
    float acc[2][4];
    #pragma unroll
    for (int m = 0; m < 2; m++)
        #pragma unroll
        for (int j = 0; j < 4; j++) acc[m][j] = 0.f;
    #pragma unroll
    for (int m = 0; m < 2; m++) {
        #pragma unroll
        for (int kc = 0; kc < 4; kc++) {
            u32 a[4];
            ldsm_x4(a, wbase + ((m * 16 + l15) * 72 + kc * 16 + lh * 8) * 2);
            mma_bf16(acc[m], a, qf[kc]);
        }
    }

    // softmax over S=8 per row (row's 8 logits live in one quad)
    float den0 = 0.f, den1 = 0.f;
    float* paw = sAb + warp * 256;
    #pragma unroll
    for (int m = 0; m < 2; m++) {
        #pragma unroll
        for (int h = 0; h < 2; h++) {
            float e0 = acc[m][h * 2]     * 0.125f;
            float e1 = acc[m][h * 2 + 1] * 0.125f;
            float mx = fmaxf(e0, e1);
            mx = fmaxf(mx, __shfl_xor_sync(0xffffffffu, mx, 1));
            mx = fmaxf(mx, __shfl_xor_sync(0xffffffffu, mx, 2));
            e0 = __expf(e0 - mx); e1 = __expf(e1 - mx);
            float se = e0 + e1;
            se += __shfl_xor_sync(0xffffffffu, se, 1);
            se += __shfl_xor_sync(0xffffffffu, se, 2);
            float inv = 1.f / se;
            e0 = e0 * inv + ATTN_EPS;
            e1 = e1 * inv + ATTN_EPS;
            int row = m * 16 + h * 8 + q;
            paw[row * 8 + c0]     = e0;
            paw[row * 8 + c0 + 1] = e1;
            den0 += e0; den1 += e1;
        }
    }
    den0 += __shfl_xor_sync(0xffffffffu, den0, 4);
    den0 += __shfl_xor_sync(0xffffffffu, den0, 8);
    den0 += __shfl_xor_sync(0xffffffffu, den0, 16);
    den1 += __shfl_xor_sync(0xffffffffu, den1, 4);
    den1 += __shfl_xor_sync(0xffffffffu, den1, 8);
    den1 += __shfl_xor_sync(0xffffffffu, den1, 16);
    __syncwarp();

    // numer[s][2 cols per lane] over the 32 rows (v from registers)
    float acc0[8], acc1[8];
    #pragma unroll
    for (int s = 0; s < 8; s++) { acc0[s] = 0.f; acc1[s] = 0.f; }
    #pragma unroll 4
    for (int i = 0; i < 32; i++) {
        float2 v = u2f2(vreg[i]);
        float4 a0 = *(const float4*)(paw + i * 8);
        float4 a1 = *(const float4*)(paw + i * 8 + 4);
        acc0[0] += a0.x * v.x; acc1[0] += a0.x * v.y;
        acc0[1] += a0.y * v.x; acc1[1] += a0.y * v.y;
        acc0[2] += a0.z * v.x; acc1[2] += a0.z * v.y;
        acc0[3] += a0.w * v.x; acc1[3] += a0.w * v.y;
        acc0[4] += a1.x * v.x; acc1[4] += a1.x * v.y;
        acc0[5] += a1.y * v.x; acc1[5] += a1.y * v.y;
        acc0[6] += a1.z * v.x; acc1[6] += a1.z * v.y;
        acc0[7] += a1.w * v.x; acc1[7] += a1.w * v.y;
    }

    float* wa = wacc + warp * 520;
    #pragma unroll
    for (int s = 0; s < 8; s++) {
        wa[s * 64 + lane * 2]     = acc0[s];
        wa[s * 64 + lane * 2 + 1] = acc1[s];
    }
    if (lane < 4) {
        wa[512 + c0]     = den0;
        wa[512 + c0 + 1] = den1;
    }
    __syncthreads();

    float* dst = g_part + (size_t)blockIdx.x * 520;
    for (int i = t; i < 520; i += 256) {
        float v = 0.f;
        #pragma unroll
        for (int w = 0; w < 8; w++) v += wacc[w * 520 + i];
        dst[i] = v;
    }
}

// ---------------------------------------------------------------------------
// update: one block per (b, slot); 4-way parallel partial reduction.
// ---------------------------------------------------------------------------
__global__ __launch_bounds__(256) void update_kernel(
    const float* __restrict__ W_ih, const float* __restrict__ W_hh,
    const float* __restrict__ b_ih, const float* __restrict__ b_hh,
    const float* __restrict__ lnmg, const float* __restrict__ lnmb,
    const float* __restrict__ mW1,  const float* __restrict__ mb1,
    const float* __restrict__ mW2,  const float* __restrict__ mb2,
    const float* __restrict__ lnsg, const float* __restrict__ lnsb,
    const float* __restrict__ Wq,
    float* __restrict__ dout)
{
    __shared__ float sRed[4][64], sDen[4];
    __shared__ float u[64], prev[64], gx[192], gh[192];
    __shared__ float snew[64], sln[64], h1[128];
    int b = blockIdx.x >> 3, s = blockIdx.x & 7;
    int t = threadIdx.x, warp = t >> 5, lane = t & 31;
    int g = t >> 6, e = t & 63;

    // ---- parallel reduction: group g sums partial blocks [16g, 16g+16) ----
    {
        const float* p = g_part + (size_t)(b * 64) * 520 + (size_t)g * 16 * 520;
        float v = 0.f;
        #pragma unroll
        for (int j = 0; j < 16; j++) v += p[j * 520 + s * 64 + e];
        sRed[g][e] = v;
        if (t < 4) {
            const float* pd = g_part + (size_t)(b * 64) * 520 + (size_t)t * 16 * 520;
            float dv = 0.f;
            #pragma unroll
            for (int j = 0; j < 16; j++) dv += pd[j * 520 + 512 + s];
            sDen[t] = dv;
        }
        if (t >= 64 && t < 128) prev[e] = g_s[b * 512 + s * 64 + e];
    }
    __syncthreads();

    if (t < 64) {
        float den = sDen[0] + sDen[1] + sDen[2] + sDen[3];
        u[t] = (sRed[0][t] + sRed[1][t] + sRed[2][t] + sRed[3][t]) / den;
    }
    __syncthreads();

    // ---- gx = u @ W_ih + b_ih ; gh = prev @ W_hh + b_hh ----
    if (t < 192) {
        float ax = b_ih[t], ah = b_hh[t];
        #pragma unroll 8
        for (int d = 0; d < 64; d++) {
            ax += u[d]    * W_ih[d * 192 + t];
            ah += prev[d] * W_hh[d * 192 + t];
        }
        gx[t] = ax; gh[t] = ah;
    }
    __syncthreads();

    if (t < 64) {
        float xr = gx[t], xz = gx[64 + t], xn = gx[128 + t];
        float hr = gh[t], hz = gh[64 + t], hn = gh[128 + t];
        float r_ = 1.f / (1.f + __expf(-(xr + hr)));
        float z  = 1.f / (1.f + __expf(-(xz + hz)));
        float nn = tanhf(xn + r_ * hn);
        snew[t] = (1.f - z) * nn + z * prev[t];
    }
    __syncthreads();

    if (warp == 0) {
        float x0 = snew[lane], x1 = snew[lane + 32];
        float s1 = x0 + x1, s2 = x0 * x0 + x1 * x1;
        #pragma unroll
        for (int o = 16; o; o >>= 1) {
            s1 += __shfl_xor_sync(0xffffffffu, s1, o);
            s2 += __shfl_xor_sync(0xffffffffu, s2, o);
        }
        float mu = s1 * 0.015625f;
        float var = s2 * 0.015625f - mu * mu;
        float rs = rsqrtf(var + LNEPS);
        sln[lane]      = (x0 - mu) * rs * lnmg[lane]      + lnmb[lane];
        sln[lane + 32] = (x1 - mu) * rs * lnmg[lane + 32] + lnmb[lane + 32];
    }
    __syncthreads();

    if (t < 128) {
        float a = mb1[t];
        #pragma unroll 8
        for (int d = 0; d < 64; d++) a += sln[d] * mW1[d * 128 + t];
        h1[t] = fmaxf(a, 0.f);
    }
    __syncthreads();

    if (t < 64) {
        float a = mb2[t];
        #pragma unroll 8
        for (int k = 0; k < 128; k++) a += h1[k] * mW2[k * 64 + t];
        float val = snew[t] + a;
        g_s[b * 512 + s * 64 + t] = val;
        dout[b * 512 + s * 64 + t] = val;
        u[t] = val;   // reuse for next-q LN
    }
    __syncthreads();

    if (warp == 0) {
        float x0 = u[lane], x1 = u[lane + 32];
        float s1 = x0 + x1, s2 = x0 * x0 + x1 * x1;
        #pragma unroll
        for (int o = 16; o; o >>= 1) {
            s1 += __shfl_xor_sync(0xffffffffu, s1, o);
            s2 += __shfl_xor_sync(0xffffffffu, s2, o);
        }
        float mu = s1 * 0.015625f;
        float var = s2 * 0.015625f - mu * mu;
        float rs = rsqrtf(var + LNEPS);
        sln[lane]      = (x0 - mu) * rs * lnsg[lane]      + lnsb[lane];
        sln[lane + 32] = (x1 - mu) * rs * lnsg[lane + 32] + lnsb[lane + 32];
    }
    __syncthreads();
    if (t < 64) {
        float a = 0.f;
        #pragma unroll 8
        for (int d = 0; d < 64; d++) a += sln[d] * Wq[d * 64 + t];
        g_q[b * 512 + s * 64 + t] = a;
    }
}

// ---------------------------------------------------------------------------
extern "C" void kernel_launch(void* const* d_in, const int* in_sizes, int n_in,
                              void* d_out, int out_size)
{
    (void)in_sizes; (void)n_in; (void)out_size;
    const float* inputs  = (const float*)d_in[0];
    const float* slots   = (const float*)d_in[1];
    const float* ln_in_g = (const float*)d_in[2];
    const float* ln_in_b = (const float*)d_in[3];
    const float* ln_s_g  = (const float*)d_in[4];
    const float* ln_s_b  = (const float*)d_in[5];
    const float* ln_m_g  = (const float*)d_in[6];
    const float* ln_m_b  = (const float*)d_in[7];
    const float* Wq      = (const float*)d_in[8];
    const float* Wk      = (const float*)d_in[9];
    const float* Wv      = (const float*)d_in[10];
    const float* W_ih    = (const float*)d_in[11];
    const float* W_hh    = (const float*)d_in[12];
    const float* b_ih    = (const float*)d_in[13];
    const float* b_hh    = (const float*)d_in[14];
    const float* mlp_W1  = (const float*)d_in[15];
    const float* mlp_b1  = (const float*)d_in[16];
    const float* mlp_W2  = (const float*)d_in[17];
    const float* mlp_b2  = (const float*)d_in[18];
    const float* pa_W    = (const float*)d_in[19];
    const float* pa_b    = (const float*)d_in[20];
    const float* pe_g    = (const float*)d_in[21];
    const float* pe_b    = (const float*)d_in[22];
    const float* pe_W1   = (const float*)d_in[23];
    const float* pe_b1   = (const float*)d_in[24];
    const float* pe_W2   = (const float*)d_in[25];
    const float* pe_b2   = (const float*)d_in[26];
    float* out = (float*)d_out;

    static int configured = 0;
    if (!configured) {
        cudaFuncSetAttribute(preprocess_kernel,
                             cudaFuncAttributeMaxDynamicSharedMemorySize, PRE_SMEM_BYTES);
        cudaFuncSetAttribute(attn_kernel,
                             cudaFuncAttributeMaxDynamicSharedMemorySize, ATTN_SMEM_BYTES);
        configured = 1;
    }

    preprocess_kernel<<<2048, 256, PRE_SMEM_BYTES>>>(
        inputs, ln_in_g, ln_in_b, Wk, Wv, pa_W, pa_b, pe_g, pe_b,
        pe_W1, pe_b1, pe_W2, pe_b2);

    initq_kernel<<<32, 256>>>(slots, ln_s_g, ln_s_b, Wq);

    for (int it = 0; it < 3; it++) {
        attn_kernel<<<2048, 256, ATTN_SMEM_BYTES>>>();
        update_kernel<<<256, 256>>>(W_ih, W_hh, b_ih, b_hh,
                                    ln_m_g, ln_m_b,
                                    mlp_W1, mlp_b1, mlp_W2, mlp_b2,
                                    ln_s_g, ln_s_b, Wq, out);
    }
}